// round 1
// baseline (speedup 1.0000x reference)
#include <cuda_runtime.h>
#include <mma.h>

using namespace nvcuda;

// ---------------- problem constants ----------------
#define BATCH   8
#define CDIM    512
#define HWDIM   128          // H == W
#define WS      8            // window size
#define NTOK    64           // tokens per window
#define HEADS   16
#define HD      32
#define NWIN    2048         // BATCH * 16 * 16
#define MTOT    131072       // total tokens == total pixels
#define QKVN    1536
#define ATTN_SCALE 0.17677669529663687f   // 32^-0.5

// ---------------- scratch (device globals; no runtime alloc) ----------------
__device__ float g_xw  [(size_t)MTOT * CDIM];   // BN1(x), windowed token-major
__device__ float g_qkv [(size_t)MTOT * QKVN];   // qkv projection
__device__ float g_ctx [(size_t)MTOT * CDIM];   // attention context (win,n,c)
__device__ float g_out [(size_t)MTOT * CDIM];   // proj output, flat (win,n,c)
__device__ float g_x1  [(size_t)MTOT * CDIM];   // x + window_reverse(out), NCHW
__device__ float g_xn2 [(size_t)MTOT * CDIM];   // BN2(x1), pixel-major
__device__ float g_h   [(size_t)MTOT * CDIM];   // gelu(fc1), pixel-major

// =====================================================================
// prep: BN + layout transform.
// window_mode=1: out[(win*64+pix)*512 + c]   (token-major, window order)
// window_mode=0: out[(((b*128)+h)*128+w)*512 + c]  (pixel-major)
// block = one (b, hb, wb) 8x8 patch; 256 threads.
// =====================================================================
__global__ __launch_bounds__(256)
void prep_kernel(const float* __restrict__ in,
                 const float* __restrict__ gamma, const float* __restrict__ beta,
                 const float* __restrict__ mean,  const float* __restrict__ var,
                 float* __restrict__ out, int window_mode)
{
    __shared__ float sscale[CDIM];
    __shared__ float sshift[CDIM];
    __shared__ float tile[64][65];

    int bx  = blockIdx.x;            // 0..2047
    int b   = bx >> 8;
    int hb  = (bx >> 4) & 15;
    int wb  = bx & 15;
    int tid = threadIdx.x;

    for (int c = tid; c < CDIM; c += 256) {
        float inv = rsqrtf(var[c] + 1e-5f);
        float sc  = gamma[c] * inv;
        sscale[c] = sc;
        sshift[c] = beta[c] - mean[c] * sc;
    }
    __syncthreads();

    int h0 = hb * 8, w0 = wb * 8;
    for (int cc = 0; cc < CDIM; cc += 64) {
        #pragma unroll
        for (int it = 0; it < 16; ++it) {
            int idx = it * 256 + tid;          // 0..4095
            int cl  = idx >> 6;
            int pix = idx & 63;
            int c   = cc + cl;
            int i   = pix >> 3, j = pix & 7;
            float v = in[(((size_t)b * CDIM + c) * HWDIM + h0 + i) * HWDIM + w0 + j];
            tile[cl][pix] = v * sscale[c] + sshift[c];
        }
        __syncthreads();
        #pragma unroll
        for (int it = 0; it < 16; ++it) {
            int idx = it * 256 + tid;
            int pix = idx >> 6;
            int cl  = idx & 63;
            size_t dst;
            if (window_mode) {
                dst = ((size_t)bx * 64 + pix) * CDIM + cc + cl;
            } else {
                int i = pix >> 3, j = pix & 7;
                size_t p = ((size_t)b * HWDIM + h0 + i) * HWDIM + w0 + j;
                dst = p * CDIM + cc + cl;
            }
            out[dst] = tile[cl][pix];
        }
        __syncthreads();
    }
}

// =====================================================================
// tf32 WMMA GEMM: C[M,N] = A[M,K] @ B + bias (+epilogue)
// B_COL=false: B row-major [K,N].  B_COL=true: B stored [N,K] row-major
// (i.e. effective B = stored^T, for the 'oc' MLP weights).
// EPI: 0 = bias; 1 = bias+exact GELU; 2 = bias + res(NCHW) -> NCHW out.
// Block tile 128x128x32, 8 warps, warp tile 64x32 (4x2 frags of 16x16x8).
// =====================================================================
#define GBM 128
#define GBN 128
#define GBK 32

template<bool B_COL, int EPI>
__global__ __launch_bounds__(256)
void gemm_tf32(const float* __restrict__ A, const float* __restrict__ Bm,
               const float* __restrict__ bias, float* __restrict__ C,
               const float* __restrict__ res,
               int M, int N, int K)
{
    __shared__ float smem[9216];          // union: As(4608)+Bs(4224) | staging(9216)
    float* As = smem;                     // [128][36]
    float* Bs = smem + 4608;              // [32][132]

    int tid  = threadIdx.x;
    int warp = tid >> 5;
    int wm   = warp >> 2;                 // 0..1
    int wn   = warp & 3;                  // 0..3
    int n0   = blockIdx.x * GBN;
    int m0   = blockIdx.y * GBM;

    wmma::fragment<wmma::accumulator, 16, 16, 8, float> acc[4][2];
    #pragma unroll
    for (int i = 0; i < 4; ++i)
        #pragma unroll
        for (int j = 0; j < 2; ++j)
            wmma::fill_fragment(acc[i][j], 0.0f);

    for (int k0 = 0; k0 < K; k0 += GBK) {
        // load A tile: 128 rows x 32 k (1024 float4)
        #pragma unroll
        for (int it = 0; it < 4; ++it) {
            int idx = it * 256 + tid;
            int r = idx >> 3, c4 = idx & 7;
            float4 v = *(const float4*)(A + (size_t)(m0 + r) * K + k0 + c4 * 4);
            *(float4*)(As + r * 36 + c4 * 4) = v;
        }
        if (!B_COL) {
            #pragma unroll
            for (int it = 0; it < 4; ++it) {
                int idx = it * 256 + tid;
                int kr = idx >> 5, nc4 = idx & 31;
                float4 v = *(const float4*)(Bm + (size_t)(k0 + kr) * N + n0 + nc4 * 4);
                *(float4*)(Bs + kr * 132 + nc4 * 4) = v;
            }
        } else {
            #pragma unroll
            for (int it = 0; it < 4; ++it) {
                int idx = it * 256 + tid;
                int nr = idx >> 3, kc4 = idx & 7;
                float4 v = *(const float4*)(Bm + (size_t)(n0 + nr) * K + k0 + kc4 * 4);
                Bs[(kc4 * 4 + 0) * 132 + nr] = v.x;
                Bs[(kc4 * 4 + 1) * 132 + nr] = v.y;
                Bs[(kc4 * 4 + 2) * 132 + nr] = v.z;
                Bs[(kc4 * 4 + 3) * 132 + nr] = v.w;
            }
        }
        __syncthreads();

        #pragma unroll
        for (int kk = 0; kk < 4; ++kk) {
            wmma::fragment<wmma::matrix_a, 16, 16, 8, wmma::precision::tf32, wmma::row_major> af[4];
            wmma::fragment<wmma::matrix_b, 16, 16, 8, wmma::precision::tf32, wmma::row_major> bf[2];
            #pragma unroll
            for (int i = 0; i < 4; ++i) {
                wmma::load_matrix_sync(af[i], As + (wm * 64 + i * 16) * 36 + kk * 8, 36);
                #pragma unroll
                for (int t = 0; t < af[i].num_elements; ++t)
                    af[i].x[t] = wmma::__float_to_tf32(af[i].x[t]);
            }
            #pragma unroll
            for (int j = 0; j < 2; ++j) {
                wmma::load_matrix_sync(bf[j], Bs + (kk * 8) * 132 + wn * 32 + j * 16, 132);
                #pragma unroll
                for (int t = 0; t < bf[j].num_elements; ++t)
                    bf[j].x[t] = wmma::__float_to_tf32(bf[j].x[t]);
            }
            #pragma unroll
            for (int i = 0; i < 4; ++i)
                #pragma unroll
                for (int j = 0; j < 2; ++j)
                    wmma::mma_sync(acc[i][j], af[i], bf[j], acc[i][j]);
        }
        __syncthreads();
    }

    // epilogue: 2 phases (wm==0 rows first, then wm==1), staging in smem
    for (int phase = 0; phase < 2; ++phase) {
        if (wm == phase) {
            float* stg = smem + wn * (64 * 36);
            #pragma unroll
            for (int i = 0; i < 4; ++i)
                #pragma unroll
                for (int j = 0; j < 2; ++j)
                    wmma::store_matrix_sync(stg + (i * 16) * 36 + j * 16, acc[i][j], 36,
                                            wmma::mem_row_major);
        }
        __syncthreads();
        #pragma unroll
        for (int it = 0; it < 32; ++it) {
            int e = it * 256 + tid;           // 0..8191
            int r, col;
            if (EPI == 2) { col = e >> 6; r = e & 63; }     // m-contiguous writes
            else          { r = e >> 7; col = e & 127; }    // n-contiguous writes
            float v = smem[(col >> 5) * (64 * 36) + r * 36 + (col & 31)];
            int n = n0 + col;
            int m = m0 + phase * 64 + r;
            v += bias[n];
            if (EPI == 1) {
                v = 0.5f * v * (1.0f + erff(v * 0.70710678118654752f));
                C[(size_t)m * N + n] = v;
            } else if (EPI == 2) {
                int bb = m >> 14, hh = (m >> 7) & 127, ww = m & 127;
                size_t oi = (((size_t)bb * CDIM + n) * HWDIM + hh) * HWDIM + ww;
                C[oi] = v + res[oi];
            } else {
                C[(size_t)m * N + n] = v;
            }
        }
        __syncthreads();
    }
}

// =====================================================================
// attention: one block per (head, window). fp32 in smem.
// =====================================================================
__global__ __launch_bounds__(256)
void attn_kernel(const float* __restrict__ qkv, const float* __restrict__ table,
                 float* __restrict__ ctx)
{
    __shared__ float qs[64][33];
    __shared__ float ks[64][33];
    __shared__ float vs[64][33];
    __shared__ float S[64][65];

    int head = blockIdx.x;       // 0..15
    int win  = blockIdx.y;       // 0..2047
    int tid  = threadIdx.x;

    size_t base = (size_t)win * 64 * QKVN + head * HD;
    #pragma unroll
    for (int it = 0; it < 8; ++it) {
        int idx = it * 256 + tid;        // 0..2047
        int n = idx >> 5, d = idx & 31;
        size_t off = base + (size_t)n * QKVN + d;
        qs[n][d] = qkv[off] * ATTN_SCALE;
        ks[n][d] = qkv[off + 512];
        vs[n][d] = qkv[off + 1024];
    }
    __syncthreads();

    int n  = tid & 63;
    int mg = tid >> 6;                   // 0..3
    int i1 = n >> 3, j1 = n & 7;
    #pragma unroll
    for (int mm = 0; mm < 16; ++mm) {
        int m = mg * 16 + mm;
        float a = 0.0f;
        #pragma unroll
        for (int d = 0; d < 32; ++d) a += qs[n][d] * ks[m][d];
        int i2 = m >> 3, j2 = m & 7;
        int ridx = (i1 - i2 + 7) * 15 + (j1 - j2 + 7);
        S[n][m] = a + table[ridx * HEADS + head];
    }
    __syncthreads();

    if (tid < 64) {
        float mx = -1e30f;
        #pragma unroll
        for (int m = 0; m < 64; ++m) mx = fmaxf(mx, S[tid][m]);
        float sum = 0.0f;
        #pragma unroll
        for (int m = 0; m < 64; ++m) { float e = expf(S[tid][m] - mx); S[tid][m] = e; sum += e; }
        float inv = 1.0f / sum;
        #pragma unroll
        for (int m = 0; m < 64; ++m) S[tid][m] *= inv;
    }
    __syncthreads();

    float o[8];
    #pragma unroll
    for (int dd = 0; dd < 8; ++dd) o[dd] = 0.0f;
    #pragma unroll
    for (int m = 0; m < 64; ++m) {
        float p = S[n][m];
        #pragma unroll
        for (int dd = 0; dd < 8; ++dd) o[dd] += p * vs[m][mg * 8 + dd];
    }
    size_t ob = ((size_t)win * 64 + n) * CDIM + head * HD + mg * 8;
    #pragma unroll
    for (int dd = 0; dd < 8; ++dd) ctx[ob + dd] = o[dd];
}

// =====================================================================
// x1 = x + window_reverse(g_out)   (torch .view reinterpretation)
// =====================================================================
__global__ __launch_bounds__(256)
void x1_kernel(const float* __restrict__ x, const float* __restrict__ flat,
               float* __restrict__ x1)
{
    int idx = blockIdx.x * 256 + threadIdx.x;    // 0 .. 67108863
    int w = idx & 127;
    int h = (idx >> 7) & 127;
    int d = (idx >> 14) & 511;
    int b = idx >> 23;
    int g = d * 16384 + (h >> 3) * 1024 + (w >> 3) * 64 + (h & 7) * 8 + (w & 7);
    x1[idx] = x[idx] + flat[(size_t)b * 8388608 + g];
}

// =====================================================================
extern "C" void kernel_launch(void* const* d_in, const int* in_sizes, int n_in,
                              void* d_out, int out_size)
{
    const float* x      = (const float*)d_in[0];
    const float* qkv_w  = (const float*)d_in[1];
    const float* qkv_b  = (const float*)d_in[2];
    const float* proj_w = (const float*)d_in[3];
    const float* proj_b = (const float*)d_in[4];
    const float* relt   = (const float*)d_in[5];
    const float* bn1g   = (const float*)d_in[6];
    const float* bn1b   = (const float*)d_in[7];
    const float* bn1m   = (const float*)d_in[8];
    const float* bn1v   = (const float*)d_in[9];
    const float* mlp_w1 = (const float*)d_in[10];
    const float* mlp_b1 = (const float*)d_in[11];
    const float* mlp_w2 = (const float*)d_in[12];
    const float* mlp_b2 = (const float*)d_in[13];
    const float* bn2g   = (const float*)d_in[14];
    const float* bn2b   = (const float*)d_in[15];
    const float* bn2m   = (const float*)d_in[16];
    const float* bn2v   = (const float*)d_in[17];
    float* out = (float*)d_out;

    float *p_xw, *p_qkv, *p_ctx, *p_out, *p_x1, *p_xn2, *p_h;
    cudaGetSymbolAddress((void**)&p_xw,  g_xw);
    cudaGetSymbolAddress((void**)&p_qkv, g_qkv);
    cudaGetSymbolAddress((void**)&p_ctx, g_ctx);
    cudaGetSymbolAddress((void**)&p_out, g_out);
    cudaGetSymbolAddress((void**)&p_x1,  g_x1);
    cudaGetSymbolAddress((void**)&p_xn2, g_xn2);
    cudaGetSymbolAddress((void**)&p_h,   g_h);

    // 1) BN1 + window partition
    prep_kernel<<<NWIN, 256>>>(x, bn1g, bn1b, bn1m, bn1v, p_xw, 1);

    // 2) QKV projection: [131072,512] @ [512,1536]
    gemm_tf32<false, 0><<<dim3(QKVN / GBN, MTOT / GBM), 256>>>(
        p_xw, qkv_w, qkv_b, p_qkv, nullptr, MTOT, QKVN, CDIM);

    // 3) windowed attention
    attn_kernel<<<dim3(HEADS, NWIN), 256>>>(p_qkv, relt, p_ctx);

    // 4) output projection: [131072,512] @ [512,512]
    gemm_tf32<false, 0><<<dim3(CDIM / GBN, MTOT / GBM), 256>>>(
        p_ctx, proj_w, proj_b, p_out, nullptr, MTOT, CDIM, CDIM);

    // 5) x1 = x + window_reverse(out)
    x1_kernel<<<(MTOT * CDIM) / 256, 256>>>(x, p_out, p_x1);

    // 6) BN2 + pixel-major transpose
    prep_kernel<<<NWIN, 256>>>(p_x1, bn2g, bn2b, bn2m, bn2v, p_xn2, 0);

    // 7) FC1 + GELU  (W1 is [o,c] -> B col-major)
    gemm_tf32<true, 1><<<dim3(CDIM / GBN, MTOT / GBM), 256>>>(
        p_xn2, mlp_w1, mlp_b1, p_h, nullptr, MTOT, CDIM, CDIM);

    // 8) FC2 + bias + residual -> NCHW output
    gemm_tf32<true, 2><<<dim3(CDIM / GBN, MTOT / GBM), 256>>>(
        p_h, mlp_w2, mlp_b2, out, p_x1, MTOT, CDIM, CDIM);
}

// round 2
// speedup vs baseline: 1.4169x; 1.4169x over previous
#include <cuda_runtime.h>
#include <cuda_fp16.h>
#include <mma.h>

using namespace nvcuda;

// ---------------- problem constants ----------------
#define BATCH   8
#define CDIM    512
#define HWDIM   128
#define WS      8
#define NTOK    64
#define HEADS   16
#define HD      32
#define NWIN    2048
#define MTOT    131072
#define QKVN    1536
#define ATTN_SCALE 0.17677669529663687f   // 32^-0.5

// ---------------- scratch (device globals; no runtime alloc) ----------------
__device__ __half g_xw  [(size_t)MTOT * CDIM];   // BN1(x), windowed token-major (half)
__device__ __half g_qkv [(size_t)MTOT * QKVN];   // qkv projection (half)
__device__ __half g_ctx [(size_t)MTOT * CDIM];   // attention context (half)
__device__ float  g_out [(size_t)MTOT * CDIM];   // proj output, flat (f32)
__device__ float  g_x1  [(size_t)MTOT * CDIM];   // x + window_reverse(out), NCHW (f32)
__device__ __half g_xn2 [(size_t)MTOT * CDIM];   // BN2(x1), pixel-major (half)
__device__ __half g_h   [(size_t)MTOT * CDIM];   // gelu(fc1), pixel-major (half)
// half weights
__device__ __half g_wqkv [CDIM * QKVN];
__device__ __half g_wproj[CDIM * CDIM];
__device__ __half g_w1   [CDIM * CDIM];
__device__ __half g_w2   [CDIM * CDIM];

// =====================================================================
// weight f32 -> f16 convert
// =====================================================================
__global__ __launch_bounds__(256)
void cvt_half_kernel(const float* __restrict__ in, __half* __restrict__ out, int n4)
{
    int i = blockIdx.x * 256 + threadIdx.x;
    if (i < n4) {
        float4 v = ((const float4*)in)[i];
        __half2* o = (__half2*)out + i * 2;
        o[0] = __floats2half2_rn(v.x, v.y);
        o[1] = __floats2half2_rn(v.z, v.w);
    }
}

// =====================================================================
// prep1: BN1 + window partition -> half token-major
// block = one (b, hb, wb) 8x8 patch; 256 threads.
// =====================================================================
__global__ __launch_bounds__(256)
void prep1_kernel(const float* __restrict__ in,
                  const float* __restrict__ gamma, const float* __restrict__ beta,
                  const float* __restrict__ mean,  const float* __restrict__ var,
                  __half* __restrict__ out)
{
    __shared__ float sscale[CDIM];
    __shared__ float sshift[CDIM];
    __shared__ float tile[64][65];

    int bx  = blockIdx.x;
    int b   = bx >> 8;
    int hb  = (bx >> 4) & 15;
    int wb  = bx & 15;
    int tid = threadIdx.x;

    for (int c = tid; c < CDIM; c += 256) {
        float inv = rsqrtf(var[c] + 1e-5f);
        float sc  = gamma[c] * inv;
        sscale[c] = sc;
        sshift[c] = beta[c] - mean[c] * sc;
    }
    __syncthreads();

    int h0 = hb * 8, w0 = wb * 8;
    for (int cc = 0; cc < CDIM; cc += 64) {
        #pragma unroll
        for (int it = 0; it < 16; ++it) {
            int idx = it * 256 + tid;
            int cl  = idx >> 6;
            int pix = idx & 63;
            int c   = cc + cl;
            int i   = pix >> 3, j = pix & 7;
            float v = in[(((size_t)b * CDIM + c) * HWDIM + h0 + i) * HWDIM + w0 + j];
            tile[cl][pix] = v * sscale[c] + sshift[c];
        }
        __syncthreads();
        #pragma unroll
        for (int it = 0; it < 16; ++it) {
            int idx = it * 256 + tid;
            int pix = idx >> 6;
            int cl  = idx & 63;
            out[((size_t)bx * 64 + pix) * CDIM + cc + cl] = __float2half(tile[cl][pix]);
        }
        __syncthreads();
    }
}

// =====================================================================
// x1 + BN2 fused: x1 = x + window_reverse(flat); xn2 = BN2(x1) pixel-major half
// =====================================================================
__global__ __launch_bounds__(256)
void x1bn2_kernel(const float* __restrict__ x, const float* __restrict__ flat,
                  const float* __restrict__ gamma, const float* __restrict__ beta,
                  const float* __restrict__ mean,  const float* __restrict__ var,
                  float* __restrict__ x1, __half* __restrict__ xn2)
{
    __shared__ float sscale[CDIM];
    __shared__ float sshift[CDIM];
    __shared__ float tile[64][65];

    int bx  = blockIdx.x;
    int b   = bx >> 8;
    int hb  = (bx >> 4) & 15;
    int wb  = bx & 15;
    int tid = threadIdx.x;

    for (int c = tid; c < CDIM; c += 256) {
        float inv = rsqrtf(var[c] + 1e-5f);
        float sc  = gamma[c] * inv;
        sscale[c] = sc;
        sshift[c] = beta[c] - mean[c] * sc;
    }
    __syncthreads();

    int h0 = hb * 8, w0 = wb * 8;
    size_t fbase = (size_t)b * 8388608 + hb * 1024 + wb * 64;
    for (int cc = 0; cc < CDIM; cc += 64) {
        #pragma unroll
        for (int it = 0; it < 16; ++it) {
            int idx = it * 256 + tid;
            int cl  = idx >> 6;
            int pix = idx & 63;
            int c   = cc + cl;
            int i   = pix >> 3, j = pix & 7;
            size_t xi = (((size_t)b * CDIM + c) * HWDIM + h0 + i) * HWDIM + w0 + j;
            float v = x[xi] + flat[fbase + (size_t)c * 16384 + pix];
            x1[xi] = v;
            tile[cl][pix] = v * sscale[c] + sshift[c];
        }
        __syncthreads();
        #pragma unroll
        for (int it = 0; it < 16; ++it) {
            int idx = it * 256 + tid;
            int pix = idx >> 6;
            int cl  = idx & 63;
            int i = pix >> 3, j = pix & 7;
            size_t p = ((size_t)b * HWDIM + h0 + i) * HWDIM + w0 + j;
            xn2[p * CDIM + cc + cl] = __float2half(tile[cl][pix]);
        }
        __syncthreads();
    }
}

// =====================================================================
// fp16 WMMA GEMM, cp.async double-buffered.
// C[M,N] = A[M,K] @ B + bias (+epilogue)
// B_COL=false: B row-major [K,N].  B_COL=true: B stored [N,K] (effective B^T).
// EPI: 0 = bias; 1 = bias+exact GELU; 2 = bias + res(NCHW) -> NCHW f32 out.
// OUT_HALF: write half (else float).
// Block tile 128x128x32, 8 warps, warp tile 64x32.
// =====================================================================
#define GBM 128
#define GBN 128
#define GBK 32
#define STAGE_BYTES 20480           // A:10240 + B:10240 per stage

__device__ __forceinline__ void cp_async16(void* dst, const void* src) {
    unsigned int d = (unsigned int)__cvta_generic_to_shared(dst);
    asm volatile("cp.async.cg.shared.global [%0], [%1], 16;\n" :: "r"(d), "l"(src));
}
__device__ __forceinline__ void cp_commit() { asm volatile("cp.async.commit_group;\n"); }
template<int W> __device__ __forceinline__ void cp_wait() {
    asm volatile("cp.async.wait_group %0;\n" :: "n"(W));
}

template<bool B_COL, int EPI, bool OUT_HALF>
__global__ __launch_bounds__(256)
void gemm_h(const __half* __restrict__ A, const __half* __restrict__ Bm,
            const float* __restrict__ bias, void* __restrict__ Cv,
            const float* __restrict__ res, int M, int N, int K)
{
    __shared__ __align__(16) unsigned char smem[2 * STAGE_BYTES];   // 40 KB

    int tid  = threadIdx.x;
    int warp = tid >> 5;
    int wm   = warp >> 2;
    int wn   = warp & 3;
    int n0   = blockIdx.x * GBN;
    int m0   = blockIdx.y * GBM;

    wmma::fragment<wmma::accumulator, 16, 16, 16, float> acc[4][2];
    #pragma unroll
    for (int i = 0; i < 4; ++i)
        #pragma unroll
        for (int j = 0; j < 2; ++j)
            wmma::fill_fragment(acc[i][j], 0.0f);

    const int ktiles = K / GBK;

    // tile loader
    auto load_tile = [&](int kt, int s) {
        int k0 = kt * GBK;
        __half* As = (__half*)(smem + s * STAGE_BYTES);
        __half* Bs = (__half*)(smem + s * STAGE_BYTES + 10240);
        #pragma unroll
        for (int it = 0; it < 2; ++it) {
            int ch = it * 256 + tid;          // 0..511
            int r = ch >> 2, c8 = ch & 3;
            cp_async16(As + r * 40 + c8 * 8, A + (size_t)(m0 + r) * K + k0 + c8 * 8);
        }
        if (B_COL) {
            #pragma unroll
            for (int it = 0; it < 2; ++it) {
                int ch = it * 256 + tid;
                int r = ch >> 2, c8 = ch & 3;
                cp_async16(Bs + r * 40 + c8 * 8, Bm + (size_t)(n0 + r) * K + k0 + c8 * 8);
            }
        } else {
            #pragma unroll
            for (int it = 0; it < 2; ++it) {
                int ch = it * 256 + tid;
                int r = ch >> 4, c8 = ch & 15;
                cp_async16(Bs + r * 136 + c8 * 8, Bm + (size_t)(k0 + r) * N + n0 + c8 * 8);
            }
        }
        cp_commit();
    };

    load_tile(0, 0);

    for (int t = 0; t < ktiles; ++t) {
        if (t + 1 < ktiles) {
            load_tile(t + 1, (t + 1) & 1);
            cp_wait<1>();
        } else {
            cp_wait<0>();
        }
        __syncthreads();

        const __half* As = (const __half*)(smem + (t & 1) * STAGE_BYTES);
        const __half* Bs = (const __half*)(smem + (t & 1) * STAGE_BYTES + 10240);

        #pragma unroll
        for (int kk = 0; kk < 2; ++kk) {
            wmma::fragment<wmma::matrix_a, 16, 16, 16, __half, wmma::row_major> af[4];
            #pragma unroll
            for (int i = 0; i < 4; ++i)
                wmma::load_matrix_sync(af[i], As + (wm * 64 + i * 16) * 40 + kk * 16, 40);
            if (B_COL) {
                wmma::fragment<wmma::matrix_b, 16, 16, 16, __half, wmma::col_major> bf[2];
                #pragma unroll
                for (int j = 0; j < 2; ++j)
                    wmma::load_matrix_sync(bf[j], Bs + (wn * 32 + j * 16) * 40 + kk * 16, 40);
                #pragma unroll
                for (int i = 0; i < 4; ++i)
                    #pragma unroll
                    for (int j = 0; j < 2; ++j)
                        wmma::mma_sync(acc[i][j], af[i], bf[j], acc[i][j]);
            } else {
                wmma::fragment<wmma::matrix_b, 16, 16, 16, __half, wmma::row_major> bf[2];
                #pragma unroll
                for (int j = 0; j < 2; ++j)
                    wmma::load_matrix_sync(bf[j], Bs + (kk * 16) * 136 + wn * 32 + j * 16, 136);
                #pragma unroll
                for (int i = 0; i < 4; ++i)
                    #pragma unroll
                    for (int j = 0; j < 2; ++j)
                        wmma::mma_sync(acc[i][j], af[i], bf[j], acc[i][j]);
            }
        }
        __syncthreads();
    }

    // epilogue: stage through smem (float), 2 phases over wm
    float* stgall = (float*)smem;
    for (int phase = 0; phase < 2; ++phase) {
        if (wm == phase) {
            float* stg = stgall + wn * (64 * 36);
            #pragma unroll
            for (int i = 0; i < 4; ++i)
                #pragma unroll
                for (int j = 0; j < 2; ++j)
                    wmma::store_matrix_sync(stg + (i * 16) * 36 + j * 16, acc[i][j], 36,
                                            wmma::mem_row_major);
        }
        __syncthreads();
        #pragma unroll
        for (int it = 0; it < 32; ++it) {
            int e = it * 256 + tid;           // 0..8191
            int r, col;
            if (EPI == 2) { col = e >> 6; r = e & 63; }
            else          { r = e >> 7; col = e & 127; }
            float v = stgall[(col >> 5) * (64 * 36) + r * 36 + (col & 31)];
            int n = n0 + col;
            int m = m0 + phase * 64 + r;
            v += bias[n];
            if (EPI == 1)
                v = 0.5f * v * (1.0f + erff(v * 0.70710678118654752f));
            if (EPI == 2) {
                int bb = m >> 14, hh = (m >> 7) & 127, ww = m & 127;
                size_t oi = (((size_t)bb * CDIM + n) * HWDIM + hh) * HWDIM + ww;
                ((float*)Cv)[oi] = v + res[oi];
            } else if (OUT_HALF) {
                ((__half*)Cv)[(size_t)m * N + n] = __float2half(v);
            } else {
                ((float*)Cv)[(size_t)m * N + n] = v;
            }
        }
        __syncthreads();
    }
}

// =====================================================================
// attention: one block per (head, window), fp32 math on half qkv.
// =====================================================================
__global__ __launch_bounds__(256)
void attn_kernel(const __half* __restrict__ qkv, const float* __restrict__ table,
                 __half* __restrict__ ctx)
{
    __shared__ float qs[64][33];
    __shared__ float ks[64][33];
    __shared__ float vs[64][33];
    __shared__ float S[64][65];

    int head = blockIdx.x;
    int win  = blockIdx.y;
    int tid  = threadIdx.x;

    size_t base = (size_t)win * 64 * QKVN + head * HD;
    #pragma unroll
    for (int it = 0; it < 8; ++it) {
        int idx = it * 256 + tid;
        int n = idx >> 5, d = idx & 31;
        size_t off = base + (size_t)n * QKVN + d;
        qs[n][d] = __half2float(qkv[off]) * ATTN_SCALE;
        ks[n][d] = __half2float(qkv[off + 512]);
        vs[n][d] = __half2float(qkv[off + 1024]);
    }
    __syncthreads();

    int n  = tid & 63;
    int mg = tid >> 6;
    int i1 = n >> 3, j1 = n & 7;
    #pragma unroll
    for (int mm = 0; mm < 16; ++mm) {
        int m = mg * 16 + mm;
        float a = 0.0f;
        #pragma unroll
        for (int d = 0; d < 32; ++d) a += qs[n][d] * ks[m][d];
        int i2 = m >> 3, j2 = m & 7;
        int ridx = (i1 - i2 + 7) * 15 + (j1 - j2 + 7);
        S[n][m] = a + table[ridx * HEADS + head];
    }
    __syncthreads();

    if (tid < 64) {
        float mx = -1e30f;
        #pragma unroll
        for (int m = 0; m < 64; ++m) mx = fmaxf(mx, S[tid][m]);
        float sum = 0.0f;
        #pragma unroll
        for (int m = 0; m < 64; ++m) { float e = expf(S[tid][m] - mx); S[tid][m] = e; sum += e; }
        float inv = 1.0f / sum;
        #pragma unroll
        for (int m = 0; m < 64; ++m) S[tid][m] *= inv;
    }
    __syncthreads();

    float o[8];
    #pragma unroll
    for (int dd = 0; dd < 8; ++dd) o[dd] = 0.0f;
    #pragma unroll
    for (int m = 0; m < 64; ++m) {
        float p = S[n][m];
        #pragma unroll
        for (int dd = 0; dd < 8; ++dd) o[dd] += p * vs[m][mg * 8 + dd];
    }
    size_t ob = ((size_t)win * 64 + n) * CDIM + head * HD + mg * 8;
    #pragma unroll
    for (int dd = 0; dd < 8; ++dd) ctx[ob + dd] = __float2half(o[dd]);
}

// =====================================================================
extern "C" void kernel_launch(void* const* d_in, const int* in_sizes, int n_in,
                              void* d_out, int out_size)
{
    const float* x      = (const float*)d_in[0];
    const float* qkv_w  = (const float*)d_in[1];
    const float* qkv_b  = (const float*)d_in[2];
    const float* proj_w = (const float*)d_in[3];
    const float* proj_b = (const float*)d_in[4];
    const float* relt   = (const float*)d_in[5];
    const float* bn1g   = (const float*)d_in[6];
    const float* bn1b   = (const float*)d_in[7];
    const float* bn1m   = (const float*)d_in[8];
    const float* bn1v   = (const float*)d_in[9];
    const float* mlp_w1 = (const float*)d_in[10];
    const float* mlp_b1 = (const float*)d_in[11];
    const float* mlp_w2 = (const float*)d_in[12];
    const float* mlp_b2 = (const float*)d_in[13];
    const float* bn2g   = (const float*)d_in[14];
    const float* bn2b   = (const float*)d_in[15];
    const float* bn2m   = (const float*)d_in[16];
    const float* bn2v   = (const float*)d_in[17];
    float* out = (float*)d_out;

    __half *p_xw, *p_qkv, *p_ctx, *p_xn2, *p_h, *p_wqkv, *p_wproj, *p_w1, *p_w2;
    float  *p_out, *p_x1;
    cudaGetSymbolAddress((void**)&p_xw,   g_xw);
    cudaGetSymbolAddress((void**)&p_qkv,  g_qkv);
    cudaGetSymbolAddress((void**)&p_ctx,  g_ctx);
    cudaGetSymbolAddress((void**)&p_out,  g_out);
    cudaGetSymbolAddress((void**)&p_x1,   g_x1);
    cudaGetSymbolAddress((void**)&p_xn2,  g_xn2);
    cudaGetSymbolAddress((void**)&p_h,    g_h);
    cudaGetSymbolAddress((void**)&p_wqkv, g_wqkv);
    cudaGetSymbolAddress((void**)&p_wproj,g_wproj);
    cudaGetSymbolAddress((void**)&p_w1,   g_w1);
    cudaGetSymbolAddress((void**)&p_w2,   g_w2);

    // 0) weight conversions (tiny)
    cvt_half_kernel<<<(CDIM * QKVN / 4 + 255) / 256, 256>>>(qkv_w,  p_wqkv, CDIM * QKVN / 4);
    cvt_half_kernel<<<(CDIM * CDIM / 4 + 255) / 256, 256>>>(proj_w, p_wproj, CDIM * CDIM / 4);
    cvt_half_kernel<<<(CDIM * CDIM / 4 + 255) / 256, 256>>>(mlp_w1, p_w1, CDIM * CDIM / 4);
    cvt_half_kernel<<<(CDIM * CDIM / 4 + 255) / 256, 256>>>(mlp_w2, p_w2, CDIM * CDIM / 4);

    // 1) BN1 + window partition
    prep1_kernel<<<NWIN, 256>>>(x, bn1g, bn1b, bn1m, bn1v, p_xw);

    // 2) QKV projection
    gemm_h<false, 0, true><<<dim3(QKVN / GBN, MTOT / GBM), 256>>>(
        p_xw, p_wqkv, qkv_b, p_qkv, nullptr, MTOT, QKVN, CDIM);

    // 3) windowed attention
    attn_kernel<<<dim3(HEADS, NWIN), 256>>>(p_qkv, relt, p_ctx);

    // 4) output projection -> flat f32
    gemm_h<false, 0, false><<<dim3(CDIM / GBN, MTOT / GBM), 256>>>(
        p_ctx, p_wproj, proj_b, p_out, nullptr, MTOT, CDIM, CDIM);

    // 5) x1 = x + window_reverse(out); BN2 + pixel-major transpose (fused)
    x1bn2_kernel<<<NWIN, 256>>>(x, p_out, bn2g, bn2b, bn2m, bn2v, p_x1, p_xn2);

    // 6) FC1 + GELU (W1 [o,c] -> col-major B)
    gemm_h<true, 1, true><<<dim3(CDIM / GBN, MTOT / GBM), 256>>>(
        p_xn2, p_w1, mlp_b1, p_h, nullptr, MTOT, CDIM, CDIM);

    // 7) FC2 + bias + residual -> NCHW output
    gemm_h<true, 2, false><<<dim3(CDIM / GBN, MTOT / GBM), 256>>>(
        p_h, p_w2, mlp_b2, out, p_x1, MTOT, CDIM, CDIM);
}

// round 4
// speedup vs baseline: 2.1795x; 1.5383x over previous
#include <cuda_runtime.h>
#include <cuda_fp16.h>
#include <mma.h>
#include <cstdint>

using namespace nvcuda;

// ---------------- problem constants ----------------
#define BATCH   8
#define CDIM    512
#define HWDIM   128
#define NWIN    2048
#define MTOT    131072
#define QKVN    1536
#define ATTN_SCALE 0.17677669529663687f   // 32^-0.5

// ---------------- scratch (device globals; no runtime alloc) ----------------
__device__ __half g_xw  [(size_t)MTOT * CDIM];
__device__ __half g_qkv [(size_t)MTOT * QKVN];
__device__ __half g_ctx [(size_t)MTOT * CDIM];
__device__ float  g_out [(size_t)MTOT * CDIM];
__device__ float  g_x1  [(size_t)MTOT * CDIM];
__device__ __half g_xn2 [(size_t)MTOT * CDIM];
__device__ __half g_h   [(size_t)MTOT * CDIM];
__device__ __half g_wqkv [CDIM * QKVN];   // [K,N]
__device__ __half g_wproj[CDIM * CDIM];   // [K,N]
__device__ __half g_w1   [CDIM * CDIM];   // [o,c] = [N,K]
__device__ __half g_w2   [CDIM * CDIM];

// =====================================================================
// weight f32 -> f16 convert (row-major copy)
// =====================================================================
__global__ __launch_bounds__(256)
void cvt_half_kernel(const float* __restrict__ in, __half* __restrict__ out, int n4)
{
    int i = blockIdx.x * 256 + threadIdx.x;
    if (i < n4) {
        float4 v = ((const float4*)in)[i];
        __half2* o = (__half2*)out + i * 2;
        o[0] = __floats2half2_rn(v.x, v.y);
        o[1] = __floats2half2_rn(v.z, v.w);
    }
}

// =====================================================================
// prep1: BN1 + window partition -> half token-major
// =====================================================================
__global__ __launch_bounds__(256)
void prep1_kernel(const float* __restrict__ in,
                  const float* __restrict__ gamma, const float* __restrict__ beta,
                  const float* __restrict__ mean,  const float* __restrict__ var,
                  __half* __restrict__ out)
{
    __shared__ float sscale[CDIM];
    __shared__ float sshift[CDIM];
    __shared__ float tile[64][65];

    int bx  = blockIdx.x;
    int b   = bx >> 8;
    int hb  = (bx >> 4) & 15;
    int wb  = bx & 15;
    int tid = threadIdx.x;

    for (int c = tid; c < CDIM; c += 256) {
        float inv = rsqrtf(var[c] + 1e-5f);
        float sc  = gamma[c] * inv;
        sscale[c] = sc;
        sshift[c] = beta[c] - mean[c] * sc;
    }
    __syncthreads();

    int h0 = hb * 8, w0 = wb * 8;
    for (int cc = 0; cc < CDIM; cc += 64) {
        #pragma unroll
        for (int it = 0; it < 16; ++it) {
            int idx = it * 256 + tid;
            int cl  = idx >> 6;
            int pix = idx & 63;
            int c   = cc + cl;
            int i   = pix >> 3, j = pix & 7;
            float v = in[(((size_t)b * CDIM + c) * HWDIM + h0 + i) * HWDIM + w0 + j];
            tile[cl][pix] = v * sscale[c] + sshift[c];
        }
        __syncthreads();
        #pragma unroll
        for (int it = 0; it < 16; ++it) {
            int idx = it * 256 + tid;
            int pix = idx >> 6;
            int cl  = idx & 63;
            out[((size_t)bx * 64 + pix) * CDIM + cc + cl] = __float2half(tile[cl][pix]);
        }
        __syncthreads();
    }
}

// =====================================================================
// x1 + BN2 fused: x1 = x + window_reverse(flat); xn2 = BN2(x1) pixel-major
// =====================================================================
__global__ __launch_bounds__(256)
void x1bn2_kernel(const float* __restrict__ x, const float* __restrict__ flat,
                  const float* __restrict__ gamma, const float* __restrict__ beta,
                  const float* __restrict__ mean,  const float* __restrict__ var,
                  float* __restrict__ x1, __half* __restrict__ xn2)
{
    __shared__ float sscale[CDIM];
    __shared__ float sshift[CDIM];
    __shared__ float tile[64][65];

    int bx  = blockIdx.x;
    int b   = bx >> 8;
    int hb  = (bx >> 4) & 15;
    int wb  = bx & 15;
    int tid = threadIdx.x;

    for (int c = tid; c < CDIM; c += 256) {
        float inv = rsqrtf(var[c] + 1e-5f);
        float sc  = gamma[c] * inv;
        sscale[c] = sc;
        sshift[c] = beta[c] - mean[c] * sc;
    }
    __syncthreads();

    int h0 = hb * 8, w0 = wb * 8;
    size_t fbase = (size_t)b * 8388608 + hb * 1024 + wb * 64;
    for (int cc = 0; cc < CDIM; cc += 64) {
        #pragma unroll
        for (int it = 0; it < 16; ++it) {
            int idx = it * 256 + tid;
            int cl  = idx >> 6;
            int pix = idx & 63;
            int c   = cc + cl;
            int i   = pix >> 3, j = pix & 7;
            size_t xi = (((size_t)b * CDIM + c) * HWDIM + h0 + i) * HWDIM + w0 + j;
            float v = x[xi] + flat[fbase + (size_t)c * 16384 + pix];
            x1[xi] = v;
            tile[cl][pix] = v * sscale[c] + sshift[c];
        }
        __syncthreads();
        #pragma unroll
        for (int it = 0; it < 16; ++it) {
            int idx = it * 256 + tid;
            int pix = idx >> 6;
            int cl  = idx & 63;
            int i = pix >> 3, j = pix & 7;
            size_t p = ((size_t)b * HWDIM + h0 + i) * HWDIM + w0 + j;
            xn2[p * CDIM + cc + cl] = __float2half(tile[cl][pix]);
        }
        __syncthreads();
    }
}

// =====================================================================
// fp16 WMMA GEMM, 3-stage cp.async, one barrier per 64-K chunk.
// C[M,N] = A[M,K] @ B + bias (+epilogue)
// B_COL=false: B row-major [K,N].  B_COL=true: B stored [N,K].
// EPI: 0 = bias; 1 = bias + exact GELU; 2 = bias + res -> NCHW f32.
// Block 128x128x64, 8 warps, warp tile 64x32.
// =====================================================================
#define GBM 128
#define GBN 128
#define GBK 64
#define NST 3
#define A_LD 72                       // 64 + 8 pad (halfs)
#define A_ST_BYTES (128 * A_LD * 2)   // 18432
#define B_LD_ROW 136                  // 128 + 8 pad
#define B_ST_BYTES 18432              // max(64*136*2=17408, 128*72*2=18432)
#define STG_BYTES (A_ST_BYTES + B_ST_BYTES)        // 36864
#define GEMM_SMEM (NST * STG_BYTES)                // 110592

__device__ __forceinline__ void cp_async16(void* dst, const void* src) {
    unsigned int d = (unsigned int)__cvta_generic_to_shared(dst);
    asm volatile("cp.async.cg.shared.global [%0], [%1], 16;\n" :: "r"(d), "l"(src));
}
__device__ __forceinline__ void cp_commit() { asm volatile("cp.async.commit_group;\n"); }
template<int W> __device__ __forceinline__ void cp_wait() {
    asm volatile("cp.async.wait_group %0;\n" :: "n"(W));
}

template<bool B_COL, int EPI, bool OUT_HALF>
__global__ __launch_bounds__(256, 1)
void gemm_h(const __half* __restrict__ A, const __half* __restrict__ Bm,
            const float* __restrict__ bias, void* __restrict__ Cv,
            const float* __restrict__ res, int M, int N, int K)
{
    extern __shared__ __align__(16) unsigned char smem[];

    int tid  = threadIdx.x;
    int warp = tid >> 5;
    int wm   = warp >> 2;
    int wn   = warp & 3;
    int n0   = blockIdx.x * GBN;
    int m0   = blockIdx.y * GBM;

    wmma::fragment<wmma::accumulator, 16, 16, 16, float> acc[4][2];
    #pragma unroll
    for (int i = 0; i < 4; ++i)
        #pragma unroll
        for (int j = 0; j < 2; ++j)
            wmma::fill_fragment(acc[i][j], 0.0f);

    const int ktiles = K / GBK;

    auto load_tile = [&](int kt, int s) {
        int k0 = kt * GBK;
        __half* As = (__half*)(smem + s * STG_BYTES);
        __half* Bs = (__half*)(smem + s * STG_BYTES + A_ST_BYTES);
        // A: 128 rows x 64 halfs = 1024 x 16B
        #pragma unroll
        for (int it = 0; it < 4; ++it) {
            int idx = it * 256 + tid;
            int r = idx >> 3, c8 = idx & 7;
            cp_async16(As + r * A_LD + c8 * 8, A + (size_t)(m0 + r) * K + k0 + c8 * 8);
        }
        if (B_COL) {
            // B: [N=128][K=64], 1024 x 16B
            #pragma unroll
            for (int it = 0; it < 4; ++it) {
                int idx = it * 256 + tid;
                int r = idx >> 3, c8 = idx & 7;
                cp_async16(Bs + r * A_LD + c8 * 8, Bm + (size_t)(n0 + r) * K + k0 + c8 * 8);
            }
        } else {
            // B: [K=64][N=128], 1024 x 16B
            #pragma unroll
            for (int it = 0; it < 4; ++it) {
                int idx = it * 256 + tid;
                int r = idx >> 4, c8 = idx & 15;
                cp_async16(Bs + r * B_LD_ROW + c8 * 8, Bm + (size_t)(k0 + r) * N + n0 + c8 * 8);
            }
        }
        cp_commit();
    };

    // prologue: 2 stages
    load_tile(0, 0);
    if (ktiles > 1) load_tile(1, 1); else cp_commit();

    for (int t = 0; t < ktiles; ++t) {
        cp_wait<NST - 2>();
        __syncthreads();

        int nt = t + NST - 1;
        if (nt < ktiles) load_tile(nt, nt % NST); else cp_commit();

        int s = t % NST;
        const __half* As = (const __half*)(smem + s * STG_BYTES);
        const __half* Bs = (const __half*)(smem + s * STG_BYTES + A_ST_BYTES);

        #pragma unroll
        for (int kk = 0; kk < 4; ++kk) {
            wmma::fragment<wmma::matrix_a, 16, 16, 16, __half, wmma::row_major> af[4];
            #pragma unroll
            for (int i = 0; i < 4; ++i)
                wmma::load_matrix_sync(af[i], As + (wm * 64 + i * 16) * A_LD + kk * 16, A_LD);
            if (B_COL) {
                wmma::fragment<wmma::matrix_b, 16, 16, 16, __half, wmma::col_major> bf[2];
                #pragma unroll
                for (int j = 0; j < 2; ++j)
                    wmma::load_matrix_sync(bf[j], Bs + (wn * 32 + j * 16) * A_LD + kk * 16, A_LD);
                #pragma unroll
                for (int i = 0; i < 4; ++i)
                    #pragma unroll
                    for (int j = 0; j < 2; ++j)
                        wmma::mma_sync(acc[i][j], af[i], bf[j], acc[i][j]);
            } else {
                wmma::fragment<wmma::matrix_b, 16, 16, 16, __half, wmma::row_major> bf[2];
                #pragma unroll
                for (int j = 0; j < 2; ++j)
                    wmma::load_matrix_sync(bf[j], Bs + (kk * 16) * B_LD_ROW + wn * 32 + j * 16, B_LD_ROW);
                #pragma unroll
                for (int i = 0; i < 4; ++i)
                    #pragma unroll
                    for (int j = 0; j < 2; ++j)
                        wmma::mma_sync(acc[i][j], af[i], bf[j], acc[i][j]);
            }
        }
    }
    __syncthreads();

    // epilogue: stage through smem (float), 2 phases over wm
    float* stgall = (float*)smem;
    for (int phase = 0; phase < 2; ++phase) {
        if (wm == phase) {
            float* stg = stgall + wn * (64 * 36);
            #pragma unroll
            for (int i = 0; i < 4; ++i)
                #pragma unroll
                for (int j = 0; j < 2; ++j)
                    wmma::store_matrix_sync(stg + (i * 16) * 36 + j * 16, acc[i][j], 36,
                                            wmma::mem_row_major);
        }
        __syncthreads();
        #pragma unroll
        for (int it = 0; it < 32; ++it) {
            int e = it * 256 + tid;
            int r, col;
            if (EPI == 2) { col = e >> 6; r = e & 63; }
            else          { r = e >> 7; col = e & 127; }
            float v = stgall[(col >> 5) * (64 * 36) + r * 36 + (col & 31)];
            int n = n0 + col;
            int m = m0 + phase * 64 + r;
            v += bias[n];
            if (EPI == 1)
                v = 0.5f * v * (1.0f + erff(v * 0.70710678118654752f));
            if (EPI == 2) {
                int bb = m >> 14, hw = m & 16383;
                size_t oi = ((size_t)bb * CDIM + n) * 16384 + hw;
                ((float*)Cv)[oi] = v + res[oi];
            } else if (OUT_HALF) {
                ((__half*)Cv)[(size_t)m * N + n] = __float2half(v);
            } else {
                ((float*)Cv)[(size_t)m * N + n] = v;
            }
        }
        __syncthreads();
    }
}

// =====================================================================
// attention: one block per (head, window), fp32 math on half qkv.
// =====================================================================
__global__ __launch_bounds__(256)
void attn_kernel(const __half* __restrict__ qkv, const float* __restrict__ table,
                 __half* __restrict__ ctx)
{
    __shared__ float qs[64][33];
    __shared__ float ks[64][33];
    __shared__ float vs[64][33];
    __shared__ float S[64][65];

    int head = blockIdx.x;
    int win  = blockIdx.y;
    int tid  = threadIdx.x;

    size_t base = (size_t)win * 64 * QKVN + head * 32;
    #pragma unroll
    for (int it = 0; it < 8; ++it) {
        int idx = it * 256 + tid;
        int n = idx >> 5, d = idx & 31;
        size_t off = base + (size_t)n * QKVN + d;
        qs[n][d] = __half2float(qkv[off]) * ATTN_SCALE;
        ks[n][d] = __half2float(qkv[off + 512]);
        vs[n][d] = __half2float(qkv[off + 1024]);
    }
    __syncthreads();

    int n  = tid & 63;
    int mg = tid >> 6;
    int i1 = n >> 3, j1 = n & 7;
    #pragma unroll
    for (int mm = 0; mm < 16; ++mm) {
        int m = mg * 16 + mm;
        float a = 0.0f;
        #pragma unroll
        for (int d = 0; d < 32; ++d) a += qs[n][d] * ks[m][d];
        int i2 = m >> 3, j2 = m & 7;
        int ridx = (i1 - i2 + 7) * 15 + (j1 - j2 + 7);
        S[n][m] = a + table[ridx * 16 + head];
    }
    __syncthreads();

    if (tid < 64) {
        float mx = -1e30f;
        #pragma unroll
        for (int m = 0; m < 64; ++m) mx = fmaxf(mx, S[tid][m]);
        float sum = 0.0f;
        #pragma unroll
        for (int m = 0; m < 64; ++m) { float e = expf(S[tid][m] - mx); S[tid][m] = e; sum += e; }
        float inv = 1.0f / sum;
        #pragma unroll
        for (int m = 0; m < 64; ++m) S[tid][m] *= inv;
    }
    __syncthreads();

    float o[8];
    #pragma unroll
    for (int dd = 0; dd < 8; ++dd) o[dd] = 0.0f;
    #pragma unroll
    for (int m = 0; m < 64; ++m) {
        float p = S[n][m];
        #pragma unroll
        for (int dd = 0; dd < 8; ++dd) o[dd] += p * vs[m][mg * 8 + dd];
    }
    size_t ob = ((size_t)win * 64 + n) * CDIM + head * 32 + mg * 8;
    #pragma unroll
    for (int dd = 0; dd < 8; ++dd) ctx[ob + dd] = __float2half(o[dd]);
}

// =====================================================================
extern "C" void kernel_launch(void* const* d_in, const int* in_sizes, int n_in,
                              void* d_out, int out_size)
{
    const float* x      = (const float*)d_in[0];
    const float* qkv_w  = (const float*)d_in[1];
    const float* qkv_b  = (const float*)d_in[2];
    const float* proj_w = (const float*)d_in[3];
    const float* proj_b = (const float*)d_in[4];
    const float* relt   = (const float*)d_in[5];
    const float* bn1g   = (const float*)d_in[6];
    const float* bn1b   = (const float*)d_in[7];
    const float* bn1m   = (const float*)d_in[8];
    const float* bn1v   = (const float*)d_in[9];
    const float* mlp_w1 = (const float*)d_in[10];
    const float* mlp_b1 = (const float*)d_in[11];
    const float* mlp_w2 = (const float*)d_in[12];
    const float* mlp_b2 = (const float*)d_in[13];
    const float* bn2g   = (const float*)d_in[14];
    const float* bn2b   = (const float*)d_in[15];
    const float* bn2m   = (const float*)d_in[16];
    const float* bn2v   = (const float*)d_in[17];
    float* out = (float*)d_out;

    __half *p_xw, *p_qkv, *p_ctx, *p_xn2, *p_h, *p_wqkv, *p_wproj, *p_w1, *p_w2;
    float  *p_out, *p_x1;
    cudaGetSymbolAddress((void**)&p_xw,   g_xw);
    cudaGetSymbolAddress((void**)&p_qkv,  g_qkv);
    cudaGetSymbolAddress((void**)&p_ctx,  g_ctx);
    cudaGetSymbolAddress((void**)&p_out,  g_out);
    cudaGetSymbolAddress((void**)&p_x1,   g_x1);
    cudaGetSymbolAddress((void**)&p_xn2,  g_xn2);
    cudaGetSymbolAddress((void**)&p_h,    g_h);
    cudaGetSymbolAddress((void**)&p_wqkv, g_wqkv);
    cudaGetSymbolAddress((void**)&p_wproj,g_wproj);
    cudaGetSymbolAddress((void**)&p_w1,   g_w1);
    cudaGetSymbolAddress((void**)&p_w2,   g_w2);

    cudaFuncSetAttribute(gemm_h<false, 0, true>,  cudaFuncAttributeMaxDynamicSharedMemorySize, GEMM_SMEM);
    cudaFuncSetAttribute(gemm_h<false, 0, false>, cudaFuncAttributeMaxDynamicSharedMemorySize, GEMM_SMEM);
    cudaFuncSetAttribute(gemm_h<true, 1, true>,   cudaFuncAttributeMaxDynamicSharedMemorySize, GEMM_SMEM);
    cudaFuncSetAttribute(gemm_h<true, 2, false>,  cudaFuncAttributeMaxDynamicSharedMemorySize, GEMM_SMEM);

    // 0) weight conversions
    cvt_half_kernel<<<(CDIM * QKVN / 4 + 255) / 256, 256>>>(qkv_w,  p_wqkv, CDIM * QKVN / 4);
    cvt_half_kernel<<<(CDIM * CDIM / 4 + 255) / 256, 256>>>(proj_w, p_wproj, CDIM * CDIM / 4);
    cvt_half_kernel<<<(CDIM * CDIM / 4 + 255) / 256, 256>>>(mlp_w1, p_w1, CDIM * CDIM / 4);
    cvt_half_kernel<<<(CDIM * CDIM / 4 + 255) / 256, 256>>>(mlp_w2, p_w2, CDIM * CDIM / 4);

    // 1) BN1 + window partition
    prep1_kernel<<<NWIN, 256>>>(x, bn1g, bn1b, bn1m, bn1v, p_xw);

    // 2) QKV projection
    gemm_h<false, 0, true><<<dim3(QKVN / GBN, MTOT / GBM), 256, GEMM_SMEM>>>(
        p_xw, p_wqkv, qkv_b, p_qkv, nullptr, MTOT, QKVN, CDIM);

    // 3) windowed attention
    attn_kernel<<<dim3(16, NWIN), 256>>>(p_qkv, relt, p_ctx);

    // 4) output projection -> flat f32
    gemm_h<false, 0, false><<<dim3(CDIM / GBN, MTOT / GBM), 256, GEMM_SMEM>>>(
        p_ctx, p_wproj, proj_b, p_out, nullptr, MTOT, CDIM, CDIM);

    // 5) x1 = x + window_reverse(out); BN2 + transpose (fused)
    x1bn2_kernel<<<NWIN, 256>>>(x, p_out, bn2g, bn2b, bn2m, bn2v, p_x1, p_xn2);

    // 6) FC1 + GELU
    gemm_h<true, 1, true><<<dim3(CDIM / GBN, MTOT / GBM), 256, GEMM_SMEM>>>(
        p_xn2, p_w1, mlp_b1, p_h, nullptr, MTOT, CDIM, CDIM);

    // 7) FC2 + bias + residual -> NCHW output
    gemm_h<true, 2, false><<<dim3(CDIM / GBN, MTOT / GBM), 256, GEMM_SMEM>>>(
        p_h, p_w2, mlp_b2, out, p_x1, MTOT, CDIM, CDIM);
}

// round 5
// speedup vs baseline: 2.3443x; 1.0756x over previous
#include <cuda_runtime.h>
#include <cuda_fp16.h>
#include <mma.h>
#include <cstdint>

using namespace nvcuda;

// ---------------- problem constants ----------------
#define BATCH   8
#define CDIM    512
#define HWDIM   128
#define NWIN    2048
#define MTOT    131072
#define QKVN    1536
#define ATTN_SCALE 0.17677669529663687f   // 32^-0.5

// ---------------- scratch (device globals; no runtime alloc) ----------------
__device__ __half g_xw  [(size_t)MTOT * CDIM];
__device__ __half g_qkv [(size_t)MTOT * QKVN];
__device__ __half g_ctx [(size_t)MTOT * CDIM];
__device__ float  g_x1  [(size_t)MTOT * CDIM];
__device__ __half g_xn2 [(size_t)MTOT * CDIM];
__device__ __half g_h   [(size_t)MTOT * CDIM];
__device__ __half g_wqkv [CDIM * QKVN];   // [K,N]
__device__ __half g_wproj[CDIM * CDIM];   // [K,N]
__device__ __half g_w1   [CDIM * CDIM];   // [o,c] = [N,K]
__device__ __half g_w2   [CDIM * CDIM];

// =====================================================================
// weight f32 -> f16 convert
// =====================================================================
__global__ __launch_bounds__(256)
void cvt_half_kernel(const float* __restrict__ in, __half* __restrict__ out, int n4)
{
    int i = blockIdx.x * 256 + threadIdx.x;
    if (i < n4) {
        float4 v = ((const float4*)in)[i];
        __half2* o = (__half2*)out + i * 2;
        o[0] = __floats2half2_rn(v.x, v.y);
        o[1] = __floats2half2_rn(v.z, v.w);
    }
}

// =====================================================================
// prep: BN + layout transform -> half.
// window_mode=1: out[(win*64+pix)*512 + c]   (token-major, window order)
// window_mode=0: out[pixel*512 + c]          (pixel-major)
// =====================================================================
__global__ __launch_bounds__(256)
void prep_kernel(const float* __restrict__ in,
                 const float* __restrict__ gamma, const float* __restrict__ beta,
                 const float* __restrict__ mean,  const float* __restrict__ var,
                 __half* __restrict__ out, int window_mode)
{
    __shared__ float sscale[CDIM];
    __shared__ float sshift[CDIM];
    __shared__ float tile[64][65];

    int bx  = blockIdx.x;
    int b   = bx >> 8;
    int hb  = (bx >> 4) & 15;
    int wb  = bx & 15;
    int tid = threadIdx.x;

    for (int c = tid; c < CDIM; c += 256) {
        float inv = rsqrtf(var[c] + 1e-5f);
        float sc  = gamma[c] * inv;
        sscale[c] = sc;
        sshift[c] = beta[c] - mean[c] * sc;
    }
    __syncthreads();

    int h0 = hb * 8, w0 = wb * 8;
    for (int cc = 0; cc < CDIM; cc += 64) {
        #pragma unroll
        for (int it = 0; it < 16; ++it) {
            int idx = it * 256 + tid;
            int cl  = idx >> 6;
            int pix = idx & 63;
            int c   = cc + cl;
            int i   = pix >> 3, j = pix & 7;
            float v = in[(((size_t)b * CDIM + c) * HWDIM + h0 + i) * HWDIM + w0 + j];
            tile[cl][pix] = v * sscale[c] + sshift[c];
        }
        __syncthreads();
        #pragma unroll
        for (int it = 0; it < 16; ++it) {
            int idx = it * 256 + tid;
            int pix = idx >> 6;
            int cl  = idx & 63;
            size_t dst;
            if (window_mode) {
                dst = ((size_t)bx * 64 + pix) * CDIM + cc + cl;
            } else {
                int i = pix >> 3, j = pix & 7;
                size_t p = ((size_t)b * HWDIM + h0 + i) * HWDIM + w0 + j;
                dst = p * CDIM + cc + cl;
            }
            out[dst] = __float2half(tile[cl][pix]);
        }
        __syncthreads();
    }
}

// =====================================================================
// fp16 WMMA GEMM, 3-stage cp.async, one barrier per 64-K chunk.
// Block 256x128x64, 8 warps (4m x 2n), warp tile 64x64.
// B_COL=false: B row-major [K,N].  B_COL=true: B stored [N,K].
// EPI: 0 = bias (half out); 1 = bias + exact GELU (half out);
//      2 = bias + res -> NCHW f32 out (fc2);
//      3 = bias + window-reverse + x residual -> NCHW f32 (proj -> x1).
// =====================================================================
#define GBM 256
#define GBN 128
#define GBK 64
#define NST 3
#define A_LD 72
#define A_ST_BYTES (GBM * A_LD * 2)          // 36864
#define B_LD_ROW 136
#define B_ST_BYTES 18432                     // max(64*136*2, 128*72*2)
#define STG_BYTES (A_ST_BYTES + B_ST_BYTES)  // 55296
#define GEMM_SMEM (NST * STG_BYTES)          // 165888
#define STG_LD 132

__device__ __forceinline__ void cp_async16(void* dst, const void* src) {
    unsigned int d = (unsigned int)__cvta_generic_to_shared(dst);
    asm volatile("cp.async.cg.shared.global [%0], [%1], 16;\n" :: "r"(d), "l"(src));
}
__device__ __forceinline__ void cp_commit() { asm volatile("cp.async.commit_group;\n"); }
template<int W> __device__ __forceinline__ void cp_wait() {
    asm volatile("cp.async.wait_group %0;\n" :: "n"(W));
}

template<bool B_COL, int EPI>
__global__ __launch_bounds__(256, 1)
void gemm_h(const __half* __restrict__ A, const __half* __restrict__ Bm,
            const float* __restrict__ bias, void* __restrict__ Cv,
            const float* __restrict__ res, int M, int N, int K)
{
    extern __shared__ __align__(16) unsigned char smem[];

    int tid  = threadIdx.x;
    int warp = tid >> 5;
    int wm   = warp >> 1;          // 0..3
    int wn   = warp & 1;           // 0..1
    int n0   = blockIdx.x * GBN;
    int m0   = blockIdx.y * GBM;

    wmma::fragment<wmma::accumulator, 16, 16, 16, float> acc[4][4];
    #pragma unroll
    for (int i = 0; i < 4; ++i)
        #pragma unroll
        for (int j = 0; j < 4; ++j)
            wmma::fill_fragment(acc[i][j], 0.0f);

    const int ktiles = K / GBK;

    auto load_tile = [&](int kt, int s) {
        int k0 = kt * GBK;
        __half* As = (__half*)(smem + s * STG_BYTES);
        __half* Bs = (__half*)(smem + s * STG_BYTES + A_ST_BYTES);
        // A: 256 rows x 64 halfs = 2048 x 16B
        #pragma unroll
        for (int it = 0; it < 8; ++it) {
            int idx = it * 256 + tid;
            int r = idx >> 3, c8 = idx & 7;
            cp_async16(As + r * A_LD + c8 * 8, A + (size_t)(m0 + r) * K + k0 + c8 * 8);
        }
        if (B_COL) {
            // [N=128][K=64]: 1024 x 16B
            #pragma unroll
            for (int it = 0; it < 4; ++it) {
                int idx = it * 256 + tid;
                int r = idx >> 3, c8 = idx & 7;
                cp_async16(Bs + r * A_LD + c8 * 8, Bm + (size_t)(n0 + r) * K + k0 + c8 * 8);
            }
        } else {
            // [K=64][N=128]: 1024 x 16B
            #pragma unroll
            for (int it = 0; it < 4; ++it) {
                int idx = it * 256 + tid;
                int r = idx >> 4, c8 = idx & 15;
                cp_async16(Bs + r * B_LD_ROW + c8 * 8, Bm + (size_t)(k0 + r) * N + n0 + c8 * 8);
            }
        }
        cp_commit();
    };

    load_tile(0, 0);
    if (ktiles > 1) load_tile(1, 1); else cp_commit();

    for (int t = 0; t < ktiles; ++t) {
        cp_wait<NST - 2>();
        __syncthreads();

        int nt = t + NST - 1;
        if (nt < ktiles) load_tile(nt, nt % NST); else cp_commit();

        int s = t % NST;
        const __half* As = (const __half*)(smem + s * STG_BYTES);
        const __half* Bs = (const __half*)(smem + s * STG_BYTES + A_ST_BYTES);

        #pragma unroll
        for (int kk = 0; kk < 4; ++kk) {
            wmma::fragment<wmma::matrix_a, 16, 16, 16, __half, wmma::row_major> af[4];
            #pragma unroll
            for (int i = 0; i < 4; ++i)
                wmma::load_matrix_sync(af[i], As + (wm * 64 + i * 16) * A_LD + kk * 16, A_LD);
            if (B_COL) {
                wmma::fragment<wmma::matrix_b, 16, 16, 16, __half, wmma::col_major> bf[4];
                #pragma unroll
                for (int j = 0; j < 4; ++j)
                    wmma::load_matrix_sync(bf[j], Bs + (wn * 64 + j * 16) * A_LD + kk * 16, A_LD);
                #pragma unroll
                for (int i = 0; i < 4; ++i)
                    #pragma unroll
                    for (int j = 0; j < 4; ++j)
                        wmma::mma_sync(acc[i][j], af[i], bf[j], acc[i][j]);
            } else {
                wmma::fragment<wmma::matrix_b, 16, 16, 16, __half, wmma::row_major> bf[4];
                #pragma unroll
                for (int j = 0; j < 4; ++j)
                    wmma::load_matrix_sync(bf[j], Bs + (kk * 16) * B_LD_ROW + wn * 64 + j * 16, B_LD_ROW);
                #pragma unroll
                for (int i = 0; i < 4; ++i)
                    #pragma unroll
                    for (int j = 0; j < 4; ++j)
                        wmma::mma_sync(acc[i][j], af[i], bf[j], acc[i][j]);
            }
        }
    }
    __syncthreads();

    // ---------------- epilogue: single-shot staging 256x128 f32 ----------------
    float* stg = (float*)smem;        // [256][STG_LD]
    #pragma unroll
    for (int i = 0; i < 4; ++i)
        #pragma unroll
        for (int j = 0; j < 4; ++j)
            wmma::store_matrix_sync(stg + (size_t)(wm * 64 + i * 16) * STG_LD + wn * 64 + j * 16,
                                    acc[i][j], STG_LD, wmma::mem_row_major);
    __syncthreads();

    #pragma unroll
    for (int it = 0; it < 16; ++it) {
        int e = it * 2048 + tid * 8;
        if (EPI == 2) {
            // r 8-consecutive, col fixed per (it, tid-group)
            int r = e & 255, col = e >> 8;
            int n = n0 + col;
            float bv = bias[n];
            int m = m0 + r;
            int bb = m >> 14, hw = m & 16383;
            size_t oi = ((size_t)bb * CDIM + n) * 16384 + hw;
            float4 o0, o1;
            const float4 r0 = *(const float4*)(res + oi);
            const float4 r1 = *(const float4*)(res + oi + 4);
            o0.x = stg[(r+0)*STG_LD+col] + bv + r0.x;
            o0.y = stg[(r+1)*STG_LD+col] + bv + r0.y;
            o0.z = stg[(r+2)*STG_LD+col] + bv + r0.z;
            o0.w = stg[(r+3)*STG_LD+col] + bv + r0.w;
            o1.x = stg[(r+4)*STG_LD+col] + bv + r1.x;
            o1.y = stg[(r+5)*STG_LD+col] + bv + r1.y;
            o1.z = stg[(r+6)*STG_LD+col] + bv + r1.z;
            o1.w = stg[(r+7)*STG_LD+col] + bv + r1.w;
            *(float4*)((float*)Cv + oi)     = o0;
            *(float4*)((float*)Cv + oi + 4) = o1;
        } else {
            int col = e & 127, r = e >> 7;     // col 8-aligned consecutive
            int m = m0 + r;
            int n = n0 + col;
            float v[8];
            #pragma unroll
            for (int j = 0; j < 8; ++j) {
                v[j] = stg[r * STG_LD + col + j] + bias[n + j];
                if (EPI == 1)
                    v[j] = 0.5f * v[j] * (1.0f + erff(v[j] * 0.70710678118654752f));
            }
            if (EPI == 3) {
                // proj -> x1: invert torch-view window reverse. m = token, n = channel.
                int bb  = m >> 14;
                int wl  = (m >> 6) & 255;
                int pix = m & 63;
                int q = wl * 32768 + pix * 512 + n;       // 8-aligned
                size_t base = (size_t)bb * 8388608 + (size_t)(q >> 14) * 16384
                            + (((q >> 10) & 15) * 8 + ((q >> 3) & 7)) * 128
                            + ((q >> 6) & 15) * 8;
                const float4 x0 = *(const float4*)(res + base);
                const float4 x1v = *(const float4*)(res + base + 4);
                float4 o0 = make_float4(v[0]+x0.x, v[1]+x0.y, v[2]+x0.z, v[3]+x0.w);
                float4 o1 = make_float4(v[4]+x1v.x, v[5]+x1v.y, v[6]+x1v.z, v[7]+x1v.w);
                *(float4*)((float*)Cv + base)     = o0;
                *(float4*)((float*)Cv + base + 4) = o1;
            } else {
                // half out, row-major [M,N]
                uint4 pk; __half2 hh;
                hh = __floats2half2_rn(v[0], v[1]); pk.x = *(unsigned*)&hh;
                hh = __floats2half2_rn(v[2], v[3]); pk.y = *(unsigned*)&hh;
                hh = __floats2half2_rn(v[4], v[5]); pk.z = *(unsigned*)&hh;
                hh = __floats2half2_rn(v[6], v[7]); pk.w = *(unsigned*)&hh;
                *(uint4*)((__half*)Cv + (size_t)m * N + n) = pk;
            }
        }
    }
}

// =====================================================================
// attention: one block per (head, window), fp32 math on half qkv.
// =====================================================================
__global__ __launch_bounds__(256)
void attn_kernel(const __half* __restrict__ qkv, const float* __restrict__ table,
                 __half* __restrict__ ctx)
{
    __shared__ float qs[64][33];
    __shared__ float ks[64][33];
    __shared__ float vs[64][33];
    __shared__ float S[64][65];

    int head = blockIdx.x;
    int win  = blockIdx.y;
    int tid  = threadIdx.x;

    size_t base = (size_t)win * 64 * QKVN + head * 32;
    #pragma unroll
    for (int it = 0; it < 8; ++it) {
        int idx = it * 256 + tid;
        int n = idx >> 5, d = idx & 31;
        size_t off = base + (size_t)n * QKVN + d;
        qs[n][d] = __half2float(qkv[off]) * ATTN_SCALE;
        ks[n][d] = __half2float(qkv[off + 512]);
        vs[n][d] = __half2float(qkv[off + 1024]);
    }
    __syncthreads();

    int n  = tid & 63;
    int mg = tid >> 6;
    int i1 = n >> 3, j1 = n & 7;
    #pragma unroll
    for (int mm = 0; mm < 16; ++mm) {
        int m = mg * 16 + mm;
        float a = 0.0f;
        #pragma unroll
        for (int d = 0; d < 32; ++d) a += qs[n][d] * ks[m][d];
        int i2 = m >> 3, j2 = m & 7;
        int ridx = (i1 - i2 + 7) * 15 + (j1 - j2 + 7);
        S[n][m] = a + table[ridx * 16 + head];
    }
    __syncthreads();

    if (tid < 64) {
        float mx = -1e30f;
        #pragma unroll
        for (int m = 0; m < 64; ++m) mx = fmaxf(mx, S[tid][m]);
        float sum = 0.0f;
        #pragma unroll
        for (int m = 0; m < 64; ++m) { float e = expf(S[tid][m] - mx); S[tid][m] = e; sum += e; }
        float inv = 1.0f / sum;
        #pragma unroll
        for (int m = 0; m < 64; ++m) S[tid][m] *= inv;
    }
    __syncthreads();

    float o[8];
    #pragma unroll
    for (int dd = 0; dd < 8; ++dd) o[dd] = 0.0f;
    #pragma unroll
    for (int m = 0; m < 64; ++m) {
        float p = S[n][m];
        #pragma unroll
        for (int dd = 0; dd < 8; ++dd) o[dd] += p * vs[m][mg * 8 + dd];
    }
    size_t ob = ((size_t)win * 64 + n) * CDIM + head * 32 + mg * 8;
    #pragma unroll
    for (int dd = 0; dd < 8; ++dd) ctx[ob + dd] = __float2half(o[dd]);
}

// =====================================================================
extern "C" void kernel_launch(void* const* d_in, const int* in_sizes, int n_in,
                              void* d_out, int out_size)
{
    const float* x      = (const float*)d_in[0];
    const float* qkv_w  = (const float*)d_in[1];
    const float* qkv_b  = (const float*)d_in[2];
    const float* proj_w = (const float*)d_in[3];
    const float* proj_b = (const float*)d_in[4];
    const float* relt   = (const float*)d_in[5];
    const float* bn1g   = (const float*)d_in[6];
    const float* bn1b   = (const float*)d_in[7];
    const float* bn1m   = (const float*)d_in[8];
    const float* bn1v   = (const float*)d_in[9];
    const float* mlp_w1 = (const float*)d_in[10];
    const float* mlp_b1 = (const float*)d_in[11];
    const float* mlp_w2 = (const float*)d_in[12];
    const float* mlp_b2 = (const float*)d_in[13];
    const float* bn2g   = (const float*)d_in[14];
    const float* bn2b   = (const float*)d_in[15];
    const float* bn2m   = (const float*)d_in[16];
    const float* bn2v   = (const float*)d_in[17];
    float* out = (float*)d_out;

    __half *p_xw, *p_qkv, *p_ctx, *p_xn2, *p_h, *p_wqkv, *p_wproj, *p_w1, *p_w2;
    float  *p_x1;
    cudaGetSymbolAddress((void**)&p_xw,   g_xw);
    cudaGetSymbolAddress((void**)&p_qkv,  g_qkv);
    cudaGetSymbolAddress((void**)&p_ctx,  g_ctx);
    cudaGetSymbolAddress((void**)&p_x1,   g_x1);
    cudaGetSymbolAddress((void**)&p_xn2,  g_xn2);
    cudaGetSymbolAddress((void**)&p_h,    g_h);
    cudaGetSymbolAddress((void**)&p_wqkv, g_wqkv);
    cudaGetSymbolAddress((void**)&p_wproj,g_wproj);
    cudaGetSymbolAddress((void**)&p_w1,   g_w1);
    cudaGetSymbolAddress((void**)&p_w2,   g_w2);

    cudaFuncSetAttribute(gemm_h<false, 0>, cudaFuncAttributeMaxDynamicSharedMemorySize, GEMM_SMEM);
    cudaFuncSetAttribute(gemm_h<false, 3>, cudaFuncAttributeMaxDynamicSharedMemorySize, GEMM_SMEM);
    cudaFuncSetAttribute(gemm_h<true, 1>,  cudaFuncAttributeMaxDynamicSharedMemorySize, GEMM_SMEM);
    cudaFuncSetAttribute(gemm_h<true, 2>,  cudaFuncAttributeMaxDynamicSharedMemorySize, GEMM_SMEM);

    // 0) weight conversions
    cvt_half_kernel<<<(CDIM * QKVN / 4 + 255) / 256, 256>>>(qkv_w,  p_wqkv, CDIM * QKVN / 4);
    cvt_half_kernel<<<(CDIM * CDIM / 4 + 255) / 256, 256>>>(proj_w, p_wproj, CDIM * CDIM / 4);
    cvt_half_kernel<<<(CDIM * CDIM / 4 + 255) / 256, 256>>>(mlp_w1, p_w1, CDIM * CDIM / 4);
    cvt_half_kernel<<<(CDIM * CDIM / 4 + 255) / 256, 256>>>(mlp_w2, p_w2, CDIM * CDIM / 4);

    // 1) BN1 + window partition
    prep_kernel<<<NWIN, 256>>>(x, bn1g, bn1b, bn1m, bn1v, p_xw, 1);

    // 2) QKV projection
    gemm_h<false, 0><<<dim3(QKVN / GBN, MTOT / GBM), 256, GEMM_SMEM>>>(
        p_xw, p_wqkv, qkv_b, p_qkv, nullptr, MTOT, QKVN, CDIM);

    // 3) windowed attention
    attn_kernel<<<dim3(16, NWIN), 256>>>(p_qkv, relt, p_ctx);

    // 4) proj + window-reverse + x residual -> x1 (NCHW f32), fused
    gemm_h<false, 3><<<dim3(CDIM / GBN, MTOT / GBM), 256, GEMM_SMEM>>>(
        p_ctx, p_wproj, proj_b, p_x1, x, MTOT, CDIM, CDIM);

    // 5) BN2 + pixel-major transpose
    prep_kernel<<<NWIN, 256>>>(p_x1, bn2g, bn2b, bn2m, bn2v, p_xn2, 0);

    // 6) FC1 + GELU
    gemm_h<true, 1><<<dim3(CDIM / GBN, MTOT / GBM), 256, GEMM_SMEM>>>(
        p_xn2, p_w1, mlp_b1, p_h, nullptr, MTOT, CDIM, CDIM);

    // 7) FC2 + bias + residual -> NCHW output
    gemm_h<true, 2><<<dim3(CDIM / GBN, MTOT / GBM), 256, GEMM_SMEM>>>(
        p_h, p_w2, mlp_b2, out, p_x1, MTOT, CDIM, CDIM);
}

// round 6
// speedup vs baseline: 3.2316x; 1.3785x over previous
#include <cuda_runtime.h>
#include <cuda_fp16.h>
#include <mma.h>
#include <cstdint>

using namespace nvcuda;

// ---------------- problem constants ----------------
#define BATCH   8
#define CDIM    512
#define HWDIM   128
#define NWIN    2048
#define MTOT    131072
#define QKVN    1536
#define ATTN_SCALE 0.17677669529663687f   // 32^-0.5

// ---------------- scratch (device globals; no runtime alloc) ----------------
__device__ __half g_xw  [(size_t)MTOT * CDIM];
__device__ __half g_qkv [(size_t)MTOT * QKVN];
__device__ __half g_ctx [(size_t)MTOT * CDIM];
__device__ float  g_x1  [(size_t)MTOT * CDIM];
__device__ __half g_xn2 [(size_t)MTOT * CDIM];
__device__ __half g_h   [(size_t)MTOT * CDIM];
__device__ __half g_wqkv [CDIM * QKVN];   // [K,N]
__device__ __half g_wproj[CDIM * CDIM];   // [K,N]
__device__ __half g_w1   [CDIM * CDIM];   // [o,c] = [N,K]
__device__ __half g_w2   [CDIM * CDIM];
__device__ float  g_bias [16 * 64 * 64];  // expanded rel-pos bias [head][n][m]

// =====================================================================
// weight f32 -> f16 convert
// =====================================================================
__global__ __launch_bounds__(256)
void cvt_half_kernel(const float* __restrict__ in, __half* __restrict__ out, int n4)
{
    int i = blockIdx.x * 256 + threadIdx.x;
    if (i < n4) {
        float4 v = ((const float4*)in)[i];
        __half2* o = (__half2*)out + i * 2;
        o[0] = __floats2half2_rn(v.x, v.y);
        o[1] = __floats2half2_rn(v.z, v.w);
    }
}

// =====================================================================
// expand rel-pos bias table -> g_bias[head][n][m]
// =====================================================================
__global__ __launch_bounds__(256)
void bias_expand_kernel(const float* __restrict__ table, float* __restrict__ out)
{
    int idx = blockIdx.x * 256 + threadIdx.x;     // 0..65535
    int m = idx & 63;
    int n = (idx >> 6) & 63;
    int h = idx >> 12;
    int i1 = n >> 3, j1 = n & 7;
    int i2 = m >> 3, j2 = m & 7;
    int ridx = (i1 - i2 + 7) * 15 + (j1 - j2 + 7);
    out[idx] = table[ridx * 16 + h];
}

// =====================================================================
// prep: BN + layout transform -> half.
// window_mode=1: out[(win*64+pix)*512 + c]; 0: out[pixel*512 + c]
// =====================================================================
__global__ __launch_bounds__(256)
void prep_kernel(const float* __restrict__ in,
                 const float* __restrict__ gamma, const float* __restrict__ beta,
                 const float* __restrict__ mean,  const float* __restrict__ var,
                 __half* __restrict__ out, int window_mode)
{
    __shared__ float sscale[CDIM];
    __shared__ float sshift[CDIM];
    __shared__ float tile[64][65];

    int bx  = blockIdx.x;
    int b   = bx >> 8;
    int hb  = (bx >> 4) & 15;
    int wb  = bx & 15;
    int tid = threadIdx.x;

    for (int c = tid; c < CDIM; c += 256) {
        float inv = rsqrtf(var[c] + 1e-5f);
        float sc  = gamma[c] * inv;
        sscale[c] = sc;
        sshift[c] = beta[c] - mean[c] * sc;
    }
    __syncthreads();

    int h0 = hb * 8, w0 = wb * 8;
    for (int cc = 0; cc < CDIM; cc += 64) {
        #pragma unroll
        for (int it = 0; it < 16; ++it) {
            int idx = it * 256 + tid;
            int cl  = idx >> 6;
            int pix = idx & 63;
            int c   = cc + cl;
            int i   = pix >> 3, j = pix & 7;
            float v = in[(((size_t)b * CDIM + c) * HWDIM + h0 + i) * HWDIM + w0 + j];
            tile[cl][pix] = v * sscale[c] + sshift[c];
        }
        __syncthreads();
        #pragma unroll
        for (int it = 0; it < 16; ++it) {
            int idx = it * 256 + tid;
            int pix = idx >> 6;
            int cl  = idx & 63;
            size_t dst;
            if (window_mode) {
                dst = ((size_t)bx * 64 + pix) * CDIM + cc + cl;
            } else {
                int i = pix >> 3, j = pix & 7;
                size_t p = ((size_t)b * HWDIM + h0 + i) * HWDIM + w0 + j;
                dst = p * CDIM + cc + cl;
            }
            out[dst] = __float2half(tile[cl][pix]);
        }
        __syncthreads();
    }
}

// =====================================================================
// fp16 WMMA GEMM, 3-stage cp.async, one barrier per 64-K chunk.
// Block 256x128x64, 8 warps (4m x 2n), warp tile 64x64.
// EPI: 0 bias->half; 1 bias+GELU->half; 2 bias+res->NCHW f32;
//      3 bias + window-reverse + x residual -> NCHW f32 (proj -> x1).
// =====================================================================
#define GBM 256
#define GBN 128
#define GBK 64
#define NST 3
#define A_LD 72
#define A_ST_BYTES (GBM * A_LD * 2)
#define B_LD_ROW 136
#define B_ST_BYTES 18432
#define STG_BYTES (A_ST_BYTES + B_ST_BYTES)
#define GEMM_SMEM (NST * STG_BYTES)
#define STG_LD 132

__device__ __forceinline__ void cp_async16(void* dst, const void* src) {
    unsigned int d = (unsigned int)__cvta_generic_to_shared(dst);
    asm volatile("cp.async.cg.shared.global [%0], [%1], 16;\n" :: "r"(d), "l"(src));
}
__device__ __forceinline__ void cp_commit() { asm volatile("cp.async.commit_group;\n"); }
template<int W> __device__ __forceinline__ void cp_wait() {
    asm volatile("cp.async.wait_group %0;\n" :: "n"(W));
}

template<bool B_COL, int EPI>
__global__ __launch_bounds__(256, 1)
void gemm_h(const __half* __restrict__ A, const __half* __restrict__ Bm,
            const float* __restrict__ bias, void* __restrict__ Cv,
            const float* __restrict__ res, int M, int N, int K)
{
    extern __shared__ __align__(16) unsigned char smem[];

    int tid  = threadIdx.x;
    int warp = tid >> 5;
    int wm   = warp >> 1;
    int wn   = warp & 1;
    int n0   = blockIdx.x * GBN;
    int m0   = blockIdx.y * GBM;

    wmma::fragment<wmma::accumulator, 16, 16, 16, float> acc[4][4];
    #pragma unroll
    for (int i = 0; i < 4; ++i)
        #pragma unroll
        for (int j = 0; j < 4; ++j)
            wmma::fill_fragment(acc[i][j], 0.0f);

    const int ktiles = K / GBK;

    auto load_tile = [&](int kt, int s) {
        int k0 = kt * GBK;
        __half* As = (__half*)(smem + s * STG_BYTES);
        __half* Bs = (__half*)(smem + s * STG_BYTES + A_ST_BYTES);
        #pragma unroll
        for (int it = 0; it < 8; ++it) {
            int idx = it * 256 + tid;
            int r = idx >> 3, c8 = idx & 7;
            cp_async16(As + r * A_LD + c8 * 8, A + (size_t)(m0 + r) * K + k0 + c8 * 8);
        }
        if (B_COL) {
            #pragma unroll
            for (int it = 0; it < 4; ++it) {
                int idx = it * 256 + tid;
                int r = idx >> 3, c8 = idx & 7;
                cp_async16(Bs + r * A_LD + c8 * 8, Bm + (size_t)(n0 + r) * K + k0 + c8 * 8);
            }
        } else {
            #pragma unroll
            for (int it = 0; it < 4; ++it) {
                int idx = it * 256 + tid;
                int r = idx >> 4, c8 = idx & 15;
                cp_async16(Bs + r * B_LD_ROW + c8 * 8, Bm + (size_t)(k0 + r) * N + n0 + c8 * 8);
            }
        }
        cp_commit();
    };

    load_tile(0, 0);
    if (ktiles > 1) load_tile(1, 1); else cp_commit();

    for (int t = 0; t < ktiles; ++t) {
        cp_wait<NST - 2>();
        __syncthreads();

        int nt = t + NST - 1;
        if (nt < ktiles) load_tile(nt, nt % NST); else cp_commit();

        int s = t % NST;
        const __half* As = (const __half*)(smem + s * STG_BYTES);
        const __half* Bs = (const __half*)(smem + s * STG_BYTES + A_ST_BYTES);

        #pragma unroll
        for (int kk = 0; kk < 4; ++kk) {
            wmma::fragment<wmma::matrix_a, 16, 16, 16, __half, wmma::row_major> af[4];
            #pragma unroll
            for (int i = 0; i < 4; ++i)
                wmma::load_matrix_sync(af[i], As + (wm * 64 + i * 16) * A_LD + kk * 16, A_LD);
            if (B_COL) {
                wmma::fragment<wmma::matrix_b, 16, 16, 16, __half, wmma::col_major> bf[4];
                #pragma unroll
                for (int j = 0; j < 4; ++j)
                    wmma::load_matrix_sync(bf[j], Bs + (wn * 64 + j * 16) * A_LD + kk * 16, A_LD);
                #pragma unroll
                for (int i = 0; i < 4; ++i)
                    #pragma unroll
                    for (int j = 0; j < 4; ++j)
                        wmma::mma_sync(acc[i][j], af[i], bf[j], acc[i][j]);
            } else {
                wmma::fragment<wmma::matrix_b, 16, 16, 16, __half, wmma::row_major> bf[4];
                #pragma unroll
                for (int j = 0; j < 4; ++j)
                    wmma::load_matrix_sync(bf[j], Bs + (kk * 16) * B_LD_ROW + wn * 64 + j * 16, B_LD_ROW);
                #pragma unroll
                for (int i = 0; i < 4; ++i)
                    #pragma unroll
                    for (int j = 0; j < 4; ++j)
                        wmma::mma_sync(acc[i][j], af[i], bf[j], acc[i][j]);
            }
        }
    }
    __syncthreads();

    float* stg = (float*)smem;
    #pragma unroll
    for (int i = 0; i < 4; ++i)
        #pragma unroll
        for (int j = 0; j < 4; ++j)
            wmma::store_matrix_sync(stg + (size_t)(wm * 64 + i * 16) * STG_LD + wn * 64 + j * 16,
                                    acc[i][j], STG_LD, wmma::mem_row_major);
    __syncthreads();

    #pragma unroll
    for (int it = 0; it < 16; ++it) {
        int e = it * 2048 + tid * 8;
        if (EPI == 2) {
            int r = e & 255, col = e >> 8;
            int n = n0 + col;
            float bv = bias[n];
            int m = m0 + r;
            int bb = m >> 14, hw = m & 16383;
            size_t oi = ((size_t)bb * CDIM + n) * 16384 + hw;
            float4 o0, o1;
            const float4 r0 = *(const float4*)(res + oi);
            const float4 r1 = *(const float4*)(res + oi + 4);
            o0.x = stg[(r+0)*STG_LD+col] + bv + r0.x;
            o0.y = stg[(r+1)*STG_LD+col] + bv + r0.y;
            o0.z = stg[(r+2)*STG_LD+col] + bv + r0.z;
            o0.w = stg[(r+3)*STG_LD+col] + bv + r0.w;
            o1.x = stg[(r+4)*STG_LD+col] + bv + r1.x;
            o1.y = stg[(r+5)*STG_LD+col] + bv + r1.y;
            o1.z = stg[(r+6)*STG_LD+col] + bv + r1.z;
            o1.w = stg[(r+7)*STG_LD+col] + bv + r1.w;
            *(float4*)((float*)Cv + oi)     = o0;
            *(float4*)((float*)Cv + oi + 4) = o1;
        } else {
            int col = e & 127, r = e >> 7;
            int m = m0 + r;
            int n = n0 + col;
            float v[8];
            #pragma unroll
            for (int j = 0; j < 8; ++j) {
                v[j] = stg[r * STG_LD + col + j] + bias[n + j];
                if (EPI == 1)
                    v[j] = 0.5f * v[j] * (1.0f + erff(v[j] * 0.70710678118654752f));
            }
            if (EPI == 3) {
                int bb  = m >> 14;
                int wl  = (m >> 6) & 255;
                int pix = m & 63;
                int q = wl * 32768 + pix * 512 + n;
                size_t base = (size_t)bb * 8388608 + (size_t)(q >> 14) * 16384
                            + (((q >> 10) & 15) * 8 + ((q >> 3) & 7)) * 128
                            + ((q >> 6) & 15) * 8;
                const float4 x0 = *(const float4*)(res + base);
                const float4 x1v = *(const float4*)(res + base + 4);
                float4 o0 = make_float4(v[0]+x0.x, v[1]+x0.y, v[2]+x0.z, v[3]+x0.w);
                float4 o1 = make_float4(v[4]+x1v.x, v[5]+x1v.y, v[6]+x1v.z, v[7]+x1v.w);
                *(float4*)((float*)Cv + base)     = o0;
                *(float4*)((float*)Cv + base + 4) = o1;
            } else {
                uint4 pk; __half2 hh;
                hh = __floats2half2_rn(v[0], v[1]); pk.x = *(unsigned*)&hh;
                hh = __floats2half2_rn(v[2], v[3]); pk.y = *(unsigned*)&hh;
                hh = __floats2half2_rn(v[4], v[5]); pk.z = *(unsigned*)&hh;
                hh = __floats2half2_rn(v[6], v[7]); pk.w = *(unsigned*)&hh;
                *(uint4*)((__half*)Cv + (size_t)m * N + n) = pk;
            }
        }
    }
}

// =====================================================================
// tensor-core attention: one block per (window, head), 64 threads (2 warps).
// QK^T and PV on wmma; fp32 softmax with pre-expanded bias.
// =====================================================================
#define QK_LD 40    // halfs
#define S_LD  68    // floats
#define P_LD  72    // halfs

__global__ __launch_bounds__(64)
void attn_tc_kernel(const __half* __restrict__ qkv, const float* __restrict__ bias16,
                    __half* __restrict__ ctx)
{
    __shared__ __align__(16) __half Qs[64 * QK_LD];
    __shared__ __align__(16) __half Ks[64 * QK_LD];
    __shared__ __align__(16) __half Vs[64 * QK_LD];
    __shared__ __align__(16) float  Ss[64 * S_LD];
    __shared__ __align__(16) __half Ps[64 * P_LD];

    int win  = blockIdx.x >> 4;
    int head = blockIdx.x & 15;
    int tid  = threadIdx.x;
    int warp = tid >> 5;

    // load Q,K,V (64 tokens x 32 halfs each), 16B chunks
    size_t base = (size_t)win * 64 * QKVN + head * 32;
    #pragma unroll
    for (int i = 0; i < 4; ++i) {
        int idx = i * 64 + tid;            // 0..255
        int tok = idx >> 2, c = idx & 3;
        size_t off = base + (size_t)tok * QKVN + c * 8;
        *(uint4*)(Qs + tok * QK_LD + c * 8) = *(const uint4*)(qkv + off);
        *(uint4*)(Ks + tok * QK_LD + c * 8) = *(const uint4*)(qkv + off + 512);
        *(uint4*)(Vs + tok * QK_LD + c * 8) = *(const uint4*)(qkv + off + 1024);
    }
    __syncthreads();

    // S = Q @ K^T   (64x64x32), warp handles 32 rows
    {
        wmma::fragment<wmma::accumulator, 16, 16, 16, float> sacc[2][4];
        #pragma unroll
        for (int i = 0; i < 2; ++i)
            #pragma unroll
            for (int j = 0; j < 4; ++j)
                wmma::fill_fragment(sacc[i][j], 0.0f);
        #pragma unroll
        for (int kk = 0; kk < 32; kk += 16) {
            wmma::fragment<wmma::matrix_a, 16, 16, 16, __half, wmma::row_major> af[2];
            wmma::fragment<wmma::matrix_b, 16, 16, 16, __half, wmma::col_major> bf[4];
            #pragma unroll
            for (int i = 0; i < 2; ++i)
                wmma::load_matrix_sync(af[i], Qs + (warp * 32 + i * 16) * QK_LD + kk, QK_LD);
            #pragma unroll
            for (int j = 0; j < 4; ++j)
                wmma::load_matrix_sync(bf[j], Ks + (j * 16) * QK_LD + kk, QK_LD);
            #pragma unroll
            for (int i = 0; i < 2; ++i)
                #pragma unroll
                for (int j = 0; j < 4; ++j)
                    wmma::mma_sync(sacc[i][j], af[i], bf[j], sacc[i][j]);
        }
        #pragma unroll
        for (int i = 0; i < 2; ++i)
            #pragma unroll
            for (int j = 0; j < 4; ++j)
                wmma::store_matrix_sync(Ss + (warp * 32 + i * 16) * S_LD + j * 16,
                                        sacc[i][j], S_LD, wmma::mem_row_major);
    }
    __syncthreads();

    // softmax row r = tid (fp32), bias from expanded table, write P half
    {
        int r = tid;
        const float* brow = bias16 + ((size_t)head * 64 + r) * 64;
        float v[64];
        float mx = -1e30f;
        #pragma unroll
        for (int q = 0; q < 16; ++q) {
            float4 s = *(float4*)(Ss + r * S_LD + q * 4);
            float4 b = *(const float4*)(brow + q * 4);
            v[q*4+0] = s.x * ATTN_SCALE + b.x;
            v[q*4+1] = s.y * ATTN_SCALE + b.y;
            v[q*4+2] = s.z * ATTN_SCALE + b.z;
            v[q*4+3] = s.w * ATTN_SCALE + b.w;
            mx = fmaxf(mx, fmaxf(fmaxf(v[q*4+0], v[q*4+1]), fmaxf(v[q*4+2], v[q*4+3])));
        }
        float sum = 0.0f;
        #pragma unroll
        for (int m = 0; m < 64; ++m) { v[m] = __expf(v[m] - mx); sum += v[m]; }
        float inv = 1.0f / sum;
        #pragma unroll
        for (int q = 0; q < 8; ++q) {
            uint4 pk; __half2 hh;
            hh = __floats2half2_rn(v[q*8+0]*inv, v[q*8+1]*inv); pk.x = *(unsigned*)&hh;
            hh = __floats2half2_rn(v[q*8+2]*inv, v[q*8+3]*inv); pk.y = *(unsigned*)&hh;
            hh = __floats2half2_rn(v[q*8+4]*inv, v[q*8+5]*inv); pk.z = *(unsigned*)&hh;
            hh = __floats2half2_rn(v[q*8+6]*inv, v[q*8+7]*inv); pk.w = *(unsigned*)&hh;
            *(uint4*)(Ps + r * P_LD + q * 8) = pk;
        }
    }
    __syncthreads();

    // O = P @ V   (64x32x64)
    {
        wmma::fragment<wmma::accumulator, 16, 16, 16, float> oacc[2][2];
        #pragma unroll
        for (int i = 0; i < 2; ++i)
            #pragma unroll
            for (int j = 0; j < 2; ++j)
                wmma::fill_fragment(oacc[i][j], 0.0f);
        #pragma unroll
        for (int kk = 0; kk < 64; kk += 16) {
            wmma::fragment<wmma::matrix_a, 16, 16, 16, __half, wmma::row_major> af[2];
            wmma::fragment<wmma::matrix_b, 16, 16, 16, __half, wmma::row_major> bf[2];
            #pragma unroll
            for (int i = 0; i < 2; ++i)
                wmma::load_matrix_sync(af[i], Ps + (warp * 32 + i * 16) * P_LD + kk, P_LD);
            #pragma unroll
            for (int j = 0; j < 2; ++j)
                wmma::load_matrix_sync(bf[j], Vs + kk * QK_LD + j * 16, QK_LD);
            #pragma unroll
            for (int i = 0; i < 2; ++i)
                #pragma unroll
                for (int j = 0; j < 2; ++j)
                    wmma::mma_sync(oacc[i][j], af[i], bf[j], oacc[i][j]);
        }
        #pragma unroll
        for (int i = 0; i < 2; ++i)
            #pragma unroll
            for (int j = 0; j < 2; ++j)
                wmma::store_matrix_sync(Ss + (warp * 32 + i * 16) * S_LD + j * 16,
                                        oacc[i][j], S_LD, wmma::mem_row_major);
    }
    __syncthreads();

    // write ctx: row r = tid, 32 halfs
    {
        int r = tid;
        size_t ob = ((size_t)win * 64 + r) * CDIM + head * 32;
        #pragma unroll
        for (int q = 0; q < 4; ++q) {
            float4 a = *(float4*)(Ss + r * S_LD + q * 8);
            float4 b = *(float4*)(Ss + r * S_LD + q * 8 + 4);
            uint4 pk; __half2 hh;
            hh = __floats2half2_rn(a.x, a.y); pk.x = *(unsigned*)&hh;
            hh = __floats2half2_rn(a.z, a.w); pk.y = *(unsigned*)&hh;
            hh = __floats2half2_rn(b.x, b.y); pk.z = *(unsigned*)&hh;
            hh = __floats2half2_rn(b.z, b.w); pk.w = *(unsigned*)&hh;
            *(uint4*)(ctx + ob + q * 8) = pk;
        }
    }
}

// =====================================================================
extern "C" void kernel_launch(void* const* d_in, const int* in_sizes, int n_in,
                              void* d_out, int out_size)
{
    const float* x      = (const float*)d_in[0];
    const float* qkv_w  = (const float*)d_in[1];
    const float* qkv_b  = (const float*)d_in[2];
    const float* proj_w = (const float*)d_in[3];
    const float* proj_b = (const float*)d_in[4];
    const float* relt   = (const float*)d_in[5];
    const float* bn1g   = (const float*)d_in[6];
    const float* bn1b   = (const float*)d_in[7];
    const float* bn1m   = (const float*)d_in[8];
    const float* bn1v   = (const float*)d_in[9];
    const float* mlp_w1 = (const float*)d_in[10];
    const float* mlp_b1 = (const float*)d_in[11];
    const float* mlp_w2 = (const float*)d_in[12];
    const float* mlp_b2 = (const float*)d_in[13];
    const float* bn2g   = (const float*)d_in[14];
    const float* bn2b   = (const float*)d_in[15];
    const float* bn2m   = (const float*)d_in[16];
    const float* bn2v   = (const float*)d_in[17];
    float* out = (float*)d_out;

    __half *p_xw, *p_qkv, *p_ctx, *p_xn2, *p_h, *p_wqkv, *p_wproj, *p_w1, *p_w2;
    float  *p_x1, *p_bias;
    cudaGetSymbolAddress((void**)&p_xw,   g_xw);
    cudaGetSymbolAddress((void**)&p_qkv,  g_qkv);
    cudaGetSymbolAddress((void**)&p_ctx,  g_ctx);
    cudaGetSymbolAddress((void**)&p_x1,   g_x1);
    cudaGetSymbolAddress((void**)&p_xn2,  g_xn2);
    cudaGetSymbolAddress((void**)&p_h,    g_h);
    cudaGetSymbolAddress((void**)&p_wqkv, g_wqkv);
    cudaGetSymbolAddress((void**)&p_wproj,g_wproj);
    cudaGetSymbolAddress((void**)&p_w1,   g_w1);
    cudaGetSymbolAddress((void**)&p_w2,   g_w2);
    cudaGetSymbolAddress((void**)&p_bias, g_bias);

    cudaFuncSetAttribute(gemm_h<false, 0>, cudaFuncAttributeMaxDynamicSharedMemorySize, GEMM_SMEM);
    cudaFuncSetAttribute(gemm_h<false, 3>, cudaFuncAttributeMaxDynamicSharedMemorySize, GEMM_SMEM);
    cudaFuncSetAttribute(gemm_h<true, 1>,  cudaFuncAttributeMaxDynamicSharedMemorySize, GEMM_SMEM);
    cudaFuncSetAttribute(gemm_h<true, 2>,  cudaFuncAttributeMaxDynamicSharedMemorySize, GEMM_SMEM);

    // 0) weight conversions + bias expansion
    cvt_half_kernel<<<(CDIM * QKVN / 4 + 255) / 256, 256>>>(qkv_w,  p_wqkv, CDIM * QKVN / 4);
    cvt_half_kernel<<<(CDIM * CDIM / 4 + 255) / 256, 256>>>(proj_w, p_wproj, CDIM * CDIM / 4);
    cvt_half_kernel<<<(CDIM * CDIM / 4 + 255) / 256, 256>>>(mlp_w1, p_w1, CDIM * CDIM / 4);
    cvt_half_kernel<<<(CDIM * CDIM / 4 + 255) / 256, 256>>>(mlp_w2, p_w2, CDIM * CDIM / 4);
    bias_expand_kernel<<<256, 256>>>(relt, p_bias);

    // 1) BN1 + window partition
    prep_kernel<<<NWIN, 256>>>(x, bn1g, bn1b, bn1m, bn1v, p_xw, 1);

    // 2) QKV projection
    gemm_h<false, 0><<<dim3(QKVN / GBN, MTOT / GBM), 256, GEMM_SMEM>>>(
        p_xw, p_wqkv, qkv_b, p_qkv, nullptr, MTOT, QKVN, CDIM);

    // 3) windowed attention (tensor cores)
    attn_tc_kernel<<<NWIN * 16, 64>>>(p_qkv, p_bias, p_ctx);

    // 4) proj + window-reverse + x residual -> x1 (NCHW f32), fused
    gemm_h<false, 3><<<dim3(CDIM / GBN, MTOT / GBM), 256, GEMM_SMEM>>>(
        p_ctx, p_wproj, proj_b, p_x1, x, MTOT, CDIM, CDIM);

    // 5) BN2 + pixel-major transpose
    prep_kernel<<<NWIN, 256>>>(p_x1, bn2g, bn2b, bn2m, bn2v, p_xn2, 0);

    // 6) FC1 + GELU
    gemm_h<true, 1><<<dim3(CDIM / GBN, MTOT / GBM), 256, GEMM_SMEM>>>(
        p_xn2, p_w1, mlp_b1, p_h, nullptr, MTOT, CDIM, CDIM);

    // 7) FC2 + bias + residual -> NCHW output
    gemm_h<true, 2><<<dim3(CDIM / GBN, MTOT / GBM), 256, GEMM_SMEM>>>(
        p_h, p_w2, mlp_b2, out, p_x1, MTOT, CDIM, CDIM);
}

// round 7
// speedup vs baseline: 3.5778x; 1.1071x over previous
#include <cuda_runtime.h>
#include <cuda_fp16.h>
#include <mma.h>
#include <cstdint>

using namespace nvcuda;

// ---------------- problem constants ----------------
#define BATCH   8
#define CDIM    512
#define HWDIM   128
#define NWIN    2048
#define MTOT    131072
#define QKVN    1536
#define ATTN_SCALE 0.17677669529663687f   // 32^-0.5

// ---------------- scratch (device globals; no runtime alloc) ----------------
__device__ __half g_xw  [(size_t)MTOT * CDIM];
__device__ __half g_qkv [(size_t)MTOT * QKVN];
__device__ __half g_ctx [(size_t)MTOT * CDIM];
__device__ float  g_x1  [(size_t)MTOT * CDIM];
__device__ __half g_xn2 [(size_t)MTOT * CDIM];
__device__ __half g_h   [(size_t)MTOT * CDIM];
__device__ __half g_wqkv [CDIM * QKVN];   // [K,N]
__device__ __half g_wproj[CDIM * CDIM];   // [K,N]
__device__ __half g_w1   [CDIM * CDIM];   // [o,c] = [N,K]
__device__ __half g_w2   [CDIM * CDIM];
__device__ float  g_bias [16 * 64 * 64];  // expanded rel-pos bias [head][n][m]

// =====================================================================
// weight f32 -> f16 convert
// =====================================================================
__global__ __launch_bounds__(256)
void cvt_half_kernel(const float* __restrict__ in, __half* __restrict__ out, int n4)
{
    int i = blockIdx.x * 256 + threadIdx.x;
    if (i < n4) {
        float4 v = ((const float4*)in)[i];
        __half2* o = (__half2*)out + i * 2;
        o[0] = __floats2half2_rn(v.x, v.y);
        o[1] = __floats2half2_rn(v.z, v.w);
    }
}

// =====================================================================
// expand rel-pos bias table -> g_bias[head][n][m]
// =====================================================================
__global__ __launch_bounds__(256)
void bias_expand_kernel(const float* __restrict__ table, float* __restrict__ out)
{
    int idx = blockIdx.x * 256 + threadIdx.x;     // 0..65535
    int m = idx & 63;
    int n = (idx >> 6) & 63;
    int h = idx >> 12;
    int i1 = n >> 3, j1 = n & 7;
    int i2 = m >> 3, j2 = m & 7;
    int ridx = (i1 - i2 + 7) * 15 + (j1 - j2 + 7);
    out[idx] = table[ridx * 16 + h];
}

// =====================================================================
// prep: BN + layout transform -> half.
// window_mode=1: out[(win*64+pix)*512 + c]; 0: out[pixel*512 + c]
// =====================================================================
__global__ __launch_bounds__(256)
void prep_kernel(const float* __restrict__ in,
                 const float* __restrict__ gamma, const float* __restrict__ beta,
                 const float* __restrict__ mean,  const float* __restrict__ var,
                 __half* __restrict__ out, int window_mode)
{
    __shared__ float sscale[CDIM];
    __shared__ float sshift[CDIM];
    __shared__ float tile[64][65];

    int bx  = blockIdx.x;
    int b   = bx >> 8;
    int hb  = (bx >> 4) & 15;
    int wb  = bx & 15;
    int tid = threadIdx.x;

    for (int c = tid; c < CDIM; c += 256) {
        float inv = rsqrtf(var[c] + 1e-5f);
        float sc  = gamma[c] * inv;
        sscale[c] = sc;
        sshift[c] = beta[c] - mean[c] * sc;
    }
    __syncthreads();

    int h0 = hb * 8, w0 = wb * 8;
    for (int cc = 0; cc < CDIM; cc += 64) {
        #pragma unroll
        for (int it = 0; it < 16; ++it) {
            int idx = it * 256 + tid;
            int cl  = idx >> 6;
            int pix = idx & 63;
            int c   = cc + cl;
            int i   = pix >> 3, j = pix & 7;
            float v = in[(((size_t)b * CDIM + c) * HWDIM + h0 + i) * HWDIM + w0 + j];
            tile[cl][pix] = v * sscale[c] + sshift[c];
        }
        __syncthreads();
        #pragma unroll
        for (int it = 0; it < 16; ++it) {
            int idx = it * 256 + tid;
            int pix = idx >> 6;
            int cl  = idx & 63;
            size_t dst;
            if (window_mode) {
                dst = ((size_t)bx * 64 + pix) * CDIM + cc + cl;
            } else {
                int i = pix >> 3, j = pix & 7;
                size_t p = ((size_t)b * HWDIM + h0 + i) * HWDIM + w0 + j;
                dst = p * CDIM + cc + cl;
            }
            out[dst] = __float2half(tile[cl][pix]);
        }
        __syncthreads();
    }
}

// =====================================================================
// fp16 WMMA GEMM, 3-stage cp.async, one barrier per 64-K chunk.
// Block 128x128x64, 4 warps (2m x 2n), warp tile 64x64. 2 CTAs/SM.
// EPI: 0 bias->half; 1 bias+GELU->half; 2 bias+res->NCHW f32;
//      3 bias + window-reverse + x residual -> NCHW f32 (proj -> x1).
// =====================================================================
#define GBM 128
#define GBN 128
#define GBK 64
#define NST 3
#define A_LD 72
#define A_ST_BYTES (GBM * A_LD * 2)          // 18432
#define B_ST_BYTES 18432                     // 128 x 72 halfs (B_COL) / 64 x 136 (row)
#define B_LD_ROW 136
#define STG_BYTES (A_ST_BYTES + B_ST_BYTES)  // 36864
#define GEMM_SMEM (NST * STG_BYTES)          // 110592
#define STG_LD 132
#define NTHR 128

__device__ __forceinline__ void cp_async16(void* dst, const void* src) {
    unsigned int d = (unsigned int)__cvta_generic_to_shared(dst);
    asm volatile("cp.async.cg.shared.global [%0], [%1], 16;\n" :: "r"(d), "l"(src));
}
__device__ __forceinline__ void cp_commit() { asm volatile("cp.async.commit_group;\n"); }
template<int W> __device__ __forceinline__ void cp_wait() {
    asm volatile("cp.async.wait_group %0;\n" :: "n"(W));
}

template<bool B_COL, int EPI>
__global__ __launch_bounds__(NTHR, 2)
void gemm_h(const __half* __restrict__ A, const __half* __restrict__ Bm,
            const float* __restrict__ bias, void* __restrict__ Cv,
            const float* __restrict__ res, int M, int N, int K)
{
    extern __shared__ __align__(16) unsigned char smem[];

    int tid  = threadIdx.x;
    int warp = tid >> 5;
    int wm   = warp >> 1;          // 0..1
    int wn   = warp & 1;           // 0..1
    int n0   = blockIdx.x * GBN;
    int m0   = blockIdx.y * GBM;

    wmma::fragment<wmma::accumulator, 16, 16, 16, float> acc[4][4];
    #pragma unroll
    for (int i = 0; i < 4; ++i)
        #pragma unroll
        for (int j = 0; j < 4; ++j)
            wmma::fill_fragment(acc[i][j], 0.0f);

    const int ktiles = K / GBK;

    auto load_tile = [&](int kt, int s) {
        int k0 = kt * GBK;
        __half* As = (__half*)(smem + s * STG_BYTES);
        __half* Bs = (__half*)(smem + s * STG_BYTES + A_ST_BYTES);
        // A: 128 rows x 64 halfs = 1024 x 16B, 128 threads -> 8 iters
        #pragma unroll
        for (int it = 0; it < 8; ++it) {
            int idx = it * NTHR + tid;
            int r = idx >> 3, c8 = idx & 7;
            cp_async16(As + r * A_LD + c8 * 8, A + (size_t)(m0 + r) * K + k0 + c8 * 8);
        }
        if (B_COL) {
            #pragma unroll
            for (int it = 0; it < 8; ++it) {
                int idx = it * NTHR + tid;
                int r = idx >> 3, c8 = idx & 7;
                cp_async16(Bs + r * A_LD + c8 * 8, Bm + (size_t)(n0 + r) * K + k0 + c8 * 8);
            }
        } else {
            #pragma unroll
            for (int it = 0; it < 8; ++it) {
                int idx = it * NTHR + tid;
                int r = idx >> 4, c8 = idx & 15;
                cp_async16(Bs + r * B_LD_ROW + c8 * 8, Bm + (size_t)(k0 + r) * N + n0 + c8 * 8);
            }
        }
        cp_commit();
    };

    load_tile(0, 0);
    if (ktiles > 1) load_tile(1, 1); else cp_commit();

    for (int t = 0; t < ktiles; ++t) {
        cp_wait<NST - 2>();
        __syncthreads();

        int nt = t + NST - 1;
        if (nt < ktiles) load_tile(nt, nt % NST); else cp_commit();

        int s = t % NST;
        const __half* As = (const __half*)(smem + s * STG_BYTES);
        const __half* Bs = (const __half*)(smem + s * STG_BYTES + A_ST_BYTES);

        #pragma unroll
        for (int kk = 0; kk < 4; ++kk) {
            wmma::fragment<wmma::matrix_a, 16, 16, 16, __half, wmma::row_major> af[4];
            #pragma unroll
            for (int i = 0; i < 4; ++i)
                wmma::load_matrix_sync(af[i], As + (wm * 64 + i * 16) * A_LD + kk * 16, A_LD);
            if (B_COL) {
                wmma::fragment<wmma::matrix_b, 16, 16, 16, __half, wmma::col_major> bf[4];
                #pragma unroll
                for (int j = 0; j < 4; ++j)
                    wmma::load_matrix_sync(bf[j], Bs + (wn * 64 + j * 16) * A_LD + kk * 16, A_LD);
                #pragma unroll
                for (int i = 0; i < 4; ++i)
                    #pragma unroll
                    for (int j = 0; j < 4; ++j)
                        wmma::mma_sync(acc[i][j], af[i], bf[j], acc[i][j]);
            } else {
                wmma::fragment<wmma::matrix_b, 16, 16, 16, __half, wmma::row_major> bf[4];
                #pragma unroll
                for (int j = 0; j < 4; ++j)
                    wmma::load_matrix_sync(bf[j], Bs + (kk * 16) * B_LD_ROW + wn * 64 + j * 16, B_LD_ROW);
                #pragma unroll
                for (int i = 0; i < 4; ++i)
                    #pragma unroll
                    for (int j = 0; j < 4; ++j)
                        wmma::mma_sync(acc[i][j], af[i], bf[j], acc[i][j]);
            }
        }
    }
    __syncthreads();

    // ---------------- epilogue: staging 128x128 f32 ----------------
    float* stg = (float*)smem;        // [128][STG_LD]
    #pragma unroll
    for (int i = 0; i < 4; ++i)
        #pragma unroll
        for (int j = 0; j < 4; ++j)
            wmma::store_matrix_sync(stg + (size_t)(wm * 64 + i * 16) * STG_LD + wn * 64 + j * 16,
                                    acc[i][j], STG_LD, wmma::mem_row_major);
    __syncthreads();

    #pragma unroll
    for (int it = 0; it < 16; ++it) {
        int e = it * (NTHR * 8) + tid * 8;        // 0..16383
        if (EPI == 2) {
            int r = e & 127, col = e >> 7;        // r 8-consecutive
            int n = n0 + col;
            float bv = bias[n];
            int m = m0 + r;
            int bb = m >> 14, hw = m & 16383;
            size_t oi = ((size_t)bb * CDIM + n) * 16384 + hw;
            float4 o0, o1;
            const float4 r0 = *(const float4*)(res + oi);
            const float4 r1 = *(const float4*)(res + oi + 4);
            o0.x = stg[(r+0)*STG_LD+col] + bv + r0.x;
            o0.y = stg[(r+1)*STG_LD+col] + bv + r0.y;
            o0.z = stg[(r+2)*STG_LD+col] + bv + r0.z;
            o0.w = stg[(r+3)*STG_LD+col] + bv + r0.w;
            o1.x = stg[(r+4)*STG_LD+col] + bv + r1.x;
            o1.y = stg[(r+5)*STG_LD+col] + bv + r1.y;
            o1.z = stg[(r+6)*STG_LD+col] + bv + r1.z;
            o1.w = stg[(r+7)*STG_LD+col] + bv + r1.w;
            *(float4*)((float*)Cv + oi)     = o0;
            *(float4*)((float*)Cv + oi + 4) = o1;
        } else {
            int col = e & 127, r = e >> 7;        // col 8-aligned consecutive
            int m = m0 + r;
            int n = n0 + col;
            float v[8];
            #pragma unroll
            for (int j = 0; j < 8; ++j) {
                v[j] = stg[r * STG_LD + col + j] + bias[n + j];
                if (EPI == 1)
                    v[j] = 0.5f * v[j] * (1.0f + erff(v[j] * 0.70710678118654752f));
            }
            if (EPI == 3) {
                int bb  = m >> 14;
                int wl  = (m >> 6) & 255;
                int pix = m & 63;
                int q = wl * 32768 + pix * 512 + n;
                size_t base = (size_t)bb * 8388608 + (size_t)(q >> 14) * 16384
                            + (((q >> 10) & 15) * 8 + ((q >> 3) & 7)) * 128
                            + ((q >> 6) & 15) * 8;
                const float4 x0 = *(const float4*)(res + base);
                const float4 x1v = *(const float4*)(res + base + 4);
                float4 o0 = make_float4(v[0]+x0.x, v[1]+x0.y, v[2]+x0.z, v[3]+x0.w);
                float4 o1 = make_float4(v[4]+x1v.x, v[5]+x1v.y, v[6]+x1v.z, v[7]+x1v.w);
                *(float4*)((float*)Cv + base)     = o0;
                *(float4*)((float*)Cv + base + 4) = o1;
            } else {
                uint4 pk; __half2 hh;
                hh = __floats2half2_rn(v[0], v[1]); pk.x = *(unsigned*)&hh;
                hh = __floats2half2_rn(v[2], v[3]); pk.y = *(unsigned*)&hh;
                hh = __floats2half2_rn(v[4], v[5]); pk.z = *(unsigned*)&hh;
                hh = __floats2half2_rn(v[6], v[7]); pk.w = *(unsigned*)&hh;
                *(uint4*)((__half*)Cv + (size_t)m * N + n) = pk;
            }
        }
    }
}

// =====================================================================
// tensor-core attention: one block per (window, head), 64 threads (2 warps).
// =====================================================================
#define QK_LD 40    // halfs
#define S_LD  68    // floats
#define P_LD  72    // halfs

__global__ __launch_bounds__(64)
void attn_tc_kernel(const __half* __restrict__ qkv, const float* __restrict__ bias16,
                    __half* __restrict__ ctx)
{
    __shared__ __align__(16) __half Qs[64 * QK_LD];
    __shared__ __align__(16) __half Ks[64 * QK_LD];
    __shared__ __align__(16) __half Vs[64 * QK_LD];
    __shared__ __align__(16) float  Ss[64 * S_LD];
    __shared__ __align__(16) __half Ps[64 * P_LD];

    int win  = blockIdx.x >> 4;
    int head = blockIdx.x & 15;
    int tid  = threadIdx.x;
    int warp = tid >> 5;

    size_t base = (size_t)win * 64 * QKVN + head * 32;
    #pragma unroll
    for (int i = 0; i < 4; ++i) {
        int idx = i * 64 + tid;
        int tok = idx >> 2, c = idx & 3;
        size_t off = base + (size_t)tok * QKVN + c * 8;
        *(uint4*)(Qs + tok * QK_LD + c * 8) = *(const uint4*)(qkv + off);
        *(uint4*)(Ks + tok * QK_LD + c * 8) = *(const uint4*)(qkv + off + 512);
        *(uint4*)(Vs + tok * QK_LD + c * 8) = *(const uint4*)(qkv + off + 1024);
    }
    __syncthreads();

    {
        wmma::fragment<wmma::accumulator, 16, 16, 16, float> sacc[2][4];
        #pragma unroll
        for (int i = 0; i < 2; ++i)
            #pragma unroll
            for (int j = 0; j < 4; ++j)
                wmma::fill_fragment(sacc[i][j], 0.0f);
        #pragma unroll
        for (int kk = 0; kk < 32; kk += 16) {
            wmma::fragment<wmma::matrix_a, 16, 16, 16, __half, wmma::row_major> af[2];
            wmma::fragment<wmma::matrix_b, 16, 16, 16, __half, wmma::col_major> bf[4];
            #pragma unroll
            for (int i = 0; i < 2; ++i)
                wmma::load_matrix_sync(af[i], Qs + (warp * 32 + i * 16) * QK_LD + kk, QK_LD);
            #pragma unroll
            for (int j = 0; j < 4; ++j)
                wmma::load_matrix_sync(bf[j], Ks + (j * 16) * QK_LD + kk, QK_LD);
            #pragma unroll
            for (int i = 0; i < 2; ++i)
                #pragma unroll
                for (int j = 0; j < 4; ++j)
                    wmma::mma_sync(sacc[i][j], af[i], bf[j], sacc[i][j]);
        }
        #pragma unroll
        for (int i = 0; i < 2; ++i)
            #pragma unroll
            for (int j = 0; j < 4; ++j)
                wmma::store_matrix_sync(Ss + (warp * 32 + i * 16) * S_LD + j * 16,
                                        sacc[i][j], S_LD, wmma::mem_row_major);
    }
    __syncthreads();

    {
        int r = tid;
        const float* brow = bias16 + ((size_t)head * 64 + r) * 64;
        float v[64];
        float mx = -1e30f;
        #pragma unroll
        for (int q = 0; q < 16; ++q) {
            float4 s = *(float4*)(Ss + r * S_LD + q * 4);
            float4 b = *(const float4*)(brow + q * 4);
            v[q*4+0] = s.x * ATTN_SCALE + b.x;
            v[q*4+1] = s.y * ATTN_SCALE + b.y;
            v[q*4+2] = s.z * ATTN_SCALE + b.z;
            v[q*4+3] = s.w * ATTN_SCALE + b.w;
            mx = fmaxf(mx, fmaxf(fmaxf(v[q*4+0], v[q*4+1]), fmaxf(v[q*4+2], v[q*4+3])));
        }
        float sum = 0.0f;
        #pragma unroll
        for (int m = 0; m < 64; ++m) { v[m] = __expf(v[m] - mx); sum += v[m]; }
        float inv = 1.0f / sum;
        #pragma unroll
        for (int q = 0; q < 8; ++q) {
            uint4 pk; __half2 hh;
            hh = __floats2half2_rn(v[q*8+0]*inv, v[q*8+1]*inv); pk.x = *(unsigned*)&hh;
            hh = __floats2half2_rn(v[q*8+2]*inv, v[q*8+3]*inv); pk.y = *(unsigned*)&hh;
            hh = __floats2half2_rn(v[q*8+4]*inv, v[q*8+5]*inv); pk.z = *(unsigned*)&hh;
            hh = __floats2half2_rn(v[q*8+6]*inv, v[q*8+7]*inv); pk.w = *(unsigned*)&hh;
            *(uint4*)(Ps + r * P_LD + q * 8) = pk;
        }
    }
    __syncthreads();

    {
        wmma::fragment<wmma::accumulator, 16, 16, 16, float> oacc[2][2];
        #pragma unroll
        for (int i = 0; i < 2; ++i)
            #pragma unroll
            for (int j = 0; j < 2; ++j)
                wmma::fill_fragment(oacc[i][j], 0.0f);
        #pragma unroll
        for (int kk = 0; kk < 64; kk += 16) {
            wmma::fragment<wmma::matrix_a, 16, 16, 16, __half, wmma::row_major> af[2];
            wmma::fragment<wmma::matrix_b, 16, 16, 16, __half, wmma::row_major> bf[2];
            #pragma unroll
            for (int i = 0; i < 2; ++i)
                wmma::load_matrix_sync(af[i], Ps + (warp * 32 + i * 16) * P_LD + kk, P_LD);
            #pragma unroll
            for (int j = 0; j < 2; ++j)
                wmma::load_matrix_sync(bf[j], Vs + kk * QK_LD + j * 16, QK_LD);
            #pragma unroll
            for (int i = 0; i < 2; ++i)
                #pragma unroll
                for (int j = 0; j < 2; ++j)
                    wmma::mma_sync(oacc[i][j], af[i], bf[j], oacc[i][j]);
        }
        #pragma unroll
        for (int i = 0; i < 2; ++i)
            #pragma unroll
            for (int j = 0; j < 2; ++j)
                wmma::store_matrix_sync(Ss + (warp * 32 + i * 16) * S_LD + j * 16,
                                        oacc[i][j], S_LD, wmma::mem_row_major);
    }
    __syncthreads();

    {
        int r = tid;
        size_t ob = ((size_t)win * 64 + r) * CDIM + head * 32;
        #pragma unroll
        for (int q = 0; q < 4; ++q) {
            float4 a = *(float4*)(Ss + r * S_LD + q * 8);
            float4 b = *(float4*)(Ss + r * S_LD + q * 8 + 4);
            uint4 pk; __half2 hh;
            hh = __floats2half2_rn(a.x, a.y); pk.x = *(unsigned*)&hh;
            hh = __floats2half2_rn(a.z, a.w); pk.y = *(unsigned*)&hh;
            hh = __floats2half2_rn(b.x, b.y); pk.z = *(unsigned*)&hh;
            hh = __floats2half2_rn(b.z, b.w); pk.w = *(unsigned*)&hh;
            *(uint4*)(ctx + ob + q * 8) = pk;
        }
    }
}

// =====================================================================
extern "C" void kernel_launch(void* const* d_in, const int* in_sizes, int n_in,
                              void* d_out, int out_size)
{
    const float* x      = (const float*)d_in[0];
    const float* qkv_w  = (const float*)d_in[1];
    const float* qkv_b  = (const float*)d_in[2];
    const float* proj_w = (const float*)d_in[3];
    const float* proj_b = (const float*)d_in[4];
    const float* relt   = (const float*)d_in[5];
    const float* bn1g   = (const float*)d_in[6];
    const float* bn1b   = (const float*)d_in[7];
    const float* bn1m   = (const float*)d_in[8];
    const float* bn1v   = (const float*)d_in[9];
    const float* mlp_w1 = (const float*)d_in[10];
    const float* mlp_b1 = (const float*)d_in[11];
    const float* mlp_w2 = (const float*)d_in[12];
    const float* mlp_b2 = (const float*)d_in[13];
    const float* bn2g   = (const float*)d_in[14];
    const float* bn2b   = (const float*)d_in[15];
    const float* bn2m   = (const float*)d_in[16];
    const float* bn2v   = (const float*)d_in[17];
    float* out = (float*)d_out;

    __half *p_xw, *p_qkv, *p_ctx, *p_xn2, *p_h, *p_wqkv, *p_wproj, *p_w1, *p_w2;
    float  *p_x1, *p_bias;
    cudaGetSymbolAddress((void**)&p_xw,   g_xw);
    cudaGetSymbolAddress((void**)&p_qkv,  g_qkv);
    cudaGetSymbolAddress((void**)&p_ctx,  g_ctx);
    cudaGetSymbolAddress((void**)&p_x1,   g_x1);
    cudaGetSymbolAddress((void**)&p_xn2,  g_xn2);
    cudaGetSymbolAddress((void**)&p_h,    g_h);
    cudaGetSymbolAddress((void**)&p_wqkv, g_wqkv);
    cudaGetSymbolAddress((void**)&p_wproj,g_wproj);
    cudaGetSymbolAddress((void**)&p_w1,   g_w1);
    cudaGetSymbolAddress((void**)&p_w2,   g_w2);
    cudaGetSymbolAddress((void**)&p_bias, g_bias);

    cudaFuncSetAttribute(gemm_h<false, 0>, cudaFuncAttributeMaxDynamicSharedMemorySize, GEMM_SMEM);
    cudaFuncSetAttribute(gemm_h<false, 3>, cudaFuncAttributeMaxDynamicSharedMemorySize, GEMM_SMEM);
    cudaFuncSetAttribute(gemm_h<true, 1>,  cudaFuncAttributeMaxDynamicSharedMemorySize, GEMM_SMEM);
    cudaFuncSetAttribute(gemm_h<true, 2>,  cudaFuncAttributeMaxDynamicSharedMemorySize, GEMM_SMEM);

    // 0) weight conversions + bias expansion
    cvt_half_kernel<<<(CDIM * QKVN / 4 + 255) / 256, 256>>>(qkv_w,  p_wqkv, CDIM * QKVN / 4);
    cvt_half_kernel<<<(CDIM * CDIM / 4 + 255) / 256, 256>>>(proj_w, p_wproj, CDIM * CDIM / 4);
    cvt_half_kernel<<<(CDIM * CDIM / 4 + 255) / 256, 256>>>(mlp_w1, p_w1, CDIM * CDIM / 4);
    cvt_half_kernel<<<(CDIM * CDIM / 4 + 255) / 256, 256>>>(mlp_w2, p_w2, CDIM * CDIM / 4);
    bias_expand_kernel<<<256, 256>>>(relt, p_bias);

    // 1) BN1 + window partition
    prep_kernel<<<NWIN, 256>>>(x, bn1g, bn1b, bn1m, bn1v, p_xw, 1);

    // 2) QKV projection
    gemm_h<false, 0><<<dim3(QKVN / GBN, MTOT / GBM), NTHR, GEMM_SMEM>>>(
        p_xw, p_wqkv, qkv_b, p_qkv, nullptr, MTOT, QKVN, CDIM);

    // 3) windowed attention (tensor cores)
    attn_tc_kernel<<<NWIN * 16, 64>>>(p_qkv, p_bias, p_ctx);

    // 4) proj + window-reverse + x residual -> x1 (NCHW f32), fused
    gemm_h<false, 3><<<dim3(CDIM / GBN, MTOT / GBM), NTHR, GEMM_SMEM>>>(
        p_ctx, p_wproj, proj_b, p_x1, x, MTOT, CDIM, CDIM);

    // 5) BN2 + pixel-major transpose
    prep_kernel<<<NWIN, 256>>>(p_x1, bn2g, bn2b, bn2m, bn2v, p_xn2, 0);

    // 6) FC1 + GELU
    gemm_h<true, 1><<<dim3(CDIM / GBN, MTOT / GBM), NTHR, GEMM_SMEM>>>(
        p_xn2, p_w1, mlp_b1, p_h, nullptr, MTOT, CDIM, CDIM);

    // 7) FC2 + bias + residual -> NCHW output
    gemm_h<true, 2><<<dim3(CDIM / GBN, MTOT / GBM), NTHR, GEMM_SMEM>>>(
        p_h, p_w2, mlp_b2, out, p_x1, MTOT, CDIM, CDIM);
}

// round 8
// speedup vs baseline: 3.8908x; 1.0875x over previous
#include <cuda_runtime.h>
#include <cuda_fp16.h>
#include <mma.h>
#include <cstdint>

using namespace nvcuda;

// ---------------- problem constants ----------------
#define BATCH   8
#define CDIM    512
#define HWDIM   128
#define NWIN    2048
#define MTOT    131072
#define QKVN    1536
#define ATTN_SCALE 0.17677669529663687f   // 32^-0.5

// ---------------- scratch (device globals; no runtime alloc) ----------------
__device__ __half g_xw  [(size_t)MTOT * CDIM];
__device__ __half g_qkv [(size_t)MTOT * QKVN];
__device__ __half g_ctx [(size_t)MTOT * CDIM];
__device__ float  g_x1  [(size_t)MTOT * CDIM];
__device__ __half g_xn2 [(size_t)MTOT * CDIM];
__device__ __half g_h   [(size_t)MTOT * CDIM];
__device__ __half g_wqkv [CDIM * QKVN];   // [K,N]
__device__ __half g_wproj[CDIM * CDIM];   // [K,N]
__device__ __half g_w1   [CDIM * CDIM];   // [o,c] = [N,K]
__device__ __half g_w2   [CDIM * CDIM];
__device__ float  g_bias [16 * 64 * 64];  // expanded rel-pos bias [head][n][m]

// =====================================================================
// batched weight f32 -> f16 convert (qkv_w: 196608 f4 | proj/w1/w2: 65536 f4 each)
// =====================================================================
__global__ __launch_bounds__(256)
void cvt_all_kernel(const float* __restrict__ w0, const float* __restrict__ w1,
                    const float* __restrict__ w2, const float* __restrict__ w3,
                    __half* __restrict__ o0, __half* __restrict__ o1,
                    __half* __restrict__ o2, __half* __restrict__ o3)
{
    int i = blockIdx.x * 256 + threadIdx.x;    // 0 .. 393215
    const float* in; __half* out; int idx;
    if (i < 196608)      { in = w0; out = o0; idx = i; }
    else if (i < 262144) { in = w1; out = o1; idx = i - 196608; }
    else if (i < 327680) { in = w2; out = o2; idx = i - 262144; }
    else                 { in = w3; out = o3; idx = i - 327680; }
    float4 v = ((const float4*)in)[idx];
    __half2* o = (__half2*)out + idx * 2;
    o[0] = __floats2half2_rn(v.x, v.y);
    o[1] = __floats2half2_rn(v.z, v.w);
}

// =====================================================================
// expand rel-pos bias table -> g_bias[head][n][m]
// =====================================================================
__global__ __launch_bounds__(256)
void bias_expand_kernel(const float* __restrict__ table, float* __restrict__ out)
{
    int idx = blockIdx.x * 256 + threadIdx.x;     // 0..65535
    int m = idx & 63;
    int n = (idx >> 6) & 63;
    int h = idx >> 12;
    int i1 = n >> 3, j1 = n & 7;
    int i2 = m >> 3, j2 = m & 7;
    int ridx = (i1 - i2 + 7) * 15 + (j1 - j2 + 7);
    out[idx] = table[ridx * 16 + h];
}

// =====================================================================
// prep: BN + layout transform -> half.
// window_mode=1: out[(win*64+pix)*512 + c]; 0: out[pixel*512 + c]
// =====================================================================
__global__ __launch_bounds__(256)
void prep_kernel(const float* __restrict__ in,
                 const float* __restrict__ gamma, const float* __restrict__ beta,
                 const float* __restrict__ mean,  const float* __restrict__ var,
                 __half* __restrict__ out, int window_mode)
{
    __shared__ float sscale[CDIM];
    __shared__ float sshift[CDIM];
    __shared__ float tile[64][65];

    int bx  = blockIdx.x;
    int b   = bx >> 8;
    int hb  = (bx >> 4) & 15;
    int wb  = bx & 15;
    int tid = threadIdx.x;

    for (int c = tid; c < CDIM; c += 256) {
        float inv = rsqrtf(var[c] + 1e-5f);
        float sc  = gamma[c] * inv;
        sscale[c] = sc;
        sshift[c] = beta[c] - mean[c] * sc;
    }
    __syncthreads();

    int h0 = hb * 8, w0 = wb * 8;
    for (int cc = 0; cc < CDIM; cc += 64) {
        #pragma unroll
        for (int it = 0; it < 16; ++it) {
            int idx = it * 256 + tid;
            int cl  = idx >> 6;
            int pix = idx & 63;
            int c   = cc + cl;
            int i   = pix >> 3, j = pix & 7;
            float v = in[(((size_t)b * CDIM + c) * HWDIM + h0 + i) * HWDIM + w0 + j];
            tile[cl][pix] = v * sscale[c] + sshift[c];
        }
        __syncthreads();
        #pragma unroll
        for (int it = 0; it < 16; ++it) {
            int idx = it * 256 + tid;
            int pix = idx >> 6;
            int cl  = idx & 63;
            size_t dst;
            if (window_mode) {
                dst = ((size_t)bx * 64 + pix) * CDIM + cc + cl;
            } else {
                int i = pix >> 3, j = pix & 7;
                size_t p = ((size_t)b * HWDIM + h0 + i) * HWDIM + w0 + j;
                dst = p * CDIM + cc + cl;
            }
            out[dst] = __float2half(tile[cl][pix]);
        }
        __syncthreads();
    }
}

// =====================================================================
// fp16 WMMA GEMM, 2-stage cp.async, 3 CTAs/SM.
// Block 128x128x64, 4 warps (2m x 2n), warp tile 64x64.
// EPI: 0 bias->half; 1 bias+GELU->half; 2 bias+res->NCHW f32;
//      3 bias + window-reverse + x residual -> NCHW f32 (proj -> x1).
// =====================================================================
#define GBM 128
#define GBN 128
#define GBK 64
#define NST 2
#define A_LD 72
#define A_ST_BYTES (GBM * A_LD * 2)          // 18432
#define B_ST_BYTES 18432
#define B_LD_ROW 136
#define STG_BYTES (A_ST_BYTES + B_ST_BYTES)  // 36864
#define GEMM_SMEM (NST * STG_BYTES)          // 73728
#define STG_LD 132
#define NTHR 128

__device__ __forceinline__ void cp_async16(void* dst, const void* src) {
    unsigned int d = (unsigned int)__cvta_generic_to_shared(dst);
    asm volatile("cp.async.cg.shared.global [%0], [%1], 16;\n" :: "r"(d), "l"(src));
}
__device__ __forceinline__ void cp_commit() { asm volatile("cp.async.commit_group;\n"); }
template<int W> __device__ __forceinline__ void cp_wait() {
    asm volatile("cp.async.wait_group %0;\n" :: "n"(W));
}

template<bool B_COL, int EPI>
__global__ __launch_bounds__(NTHR, 3)
void gemm_h(const __half* __restrict__ A, const __half* __restrict__ Bm,
            const float* __restrict__ bias, void* __restrict__ Cv,
            const float* __restrict__ res, int M, int N, int K)
{
    extern __shared__ __align__(16) unsigned char smem[];

    int tid  = threadIdx.x;
    int warp = tid >> 5;
    int wm   = warp >> 1;          // 0..1
    int wn   = warp & 1;           // 0..1
    int n0   = blockIdx.x * GBN;
    int m0   = blockIdx.y * GBM;

    wmma::fragment<wmma::accumulator, 16, 16, 16, float> acc[4][4];
    #pragma unroll
    for (int i = 0; i < 4; ++i)
        #pragma unroll
        for (int j = 0; j < 4; ++j)
            wmma::fill_fragment(acc[i][j], 0.0f);

    const int ktiles = K / GBK;

    auto load_tile = [&](int kt, int s) {
        int k0 = kt * GBK;
        __half* As = (__half*)(smem + s * STG_BYTES);
        __half* Bs = (__half*)(smem + s * STG_BYTES + A_ST_BYTES);
        #pragma unroll
        for (int it = 0; it < 8; ++it) {
            int idx = it * NTHR + tid;
            int r = idx >> 3, c8 = idx & 7;
            cp_async16(As + r * A_LD + c8 * 8, A + (size_t)(m0 + r) * K + k0 + c8 * 8);
        }
        if (B_COL) {
            #pragma unroll
            for (int it = 0; it < 8; ++it) {
                int idx = it * NTHR + tid;
                int r = idx >> 3, c8 = idx & 7;
                cp_async16(Bs + r * A_LD + c8 * 8, Bm + (size_t)(n0 + r) * K + k0 + c8 * 8);
            }
        } else {
            #pragma unroll
            for (int it = 0; it < 8; ++it) {
                int idx = it * NTHR + tid;
                int r = idx >> 4, c8 = idx & 15;
                cp_async16(Bs + r * B_LD_ROW + c8 * 8, Bm + (size_t)(k0 + r) * N + n0 + c8 * 8);
            }
        }
        cp_commit();
    };

    load_tile(0, 0);

    for (int t = 0; t < ktiles; ++t) {
        cp_wait<0>();               // stage t loaded (only outstanding group)
        __syncthreads();            // other stage fully consumed by all warps
        if (t + 1 < ktiles) load_tile(t + 1, (t + 1) & 1);

        int s = t & 1;
        const __half* As = (const __half*)(smem + s * STG_BYTES);
        const __half* Bs = (const __half*)(smem + s * STG_BYTES + A_ST_BYTES);

        #pragma unroll
        for (int kk = 0; kk < 4; ++kk) {
            wmma::fragment<wmma::matrix_a, 16, 16, 16, __half, wmma::row_major> af[4];
            #pragma unroll
            for (int i = 0; i < 4; ++i)
                wmma::load_matrix_sync(af[i], As + (wm * 64 + i * 16) * A_LD + kk * 16, A_LD);
            #pragma unroll
            for (int j = 0; j < 4; ++j) {
                if (B_COL) {
                    wmma::fragment<wmma::matrix_b, 16, 16, 16, __half, wmma::col_major> bf;
                    wmma::load_matrix_sync(bf, Bs + (wn * 64 + j * 16) * A_LD + kk * 16, A_LD);
                    #pragma unroll
                    for (int i = 0; i < 4; ++i)
                        wmma::mma_sync(acc[i][j], af[i], bf, acc[i][j]);
                } else {
                    wmma::fragment<wmma::matrix_b, 16, 16, 16, __half, wmma::row_major> bf;
                    wmma::load_matrix_sync(bf, Bs + (kk * 16) * B_LD_ROW + wn * 64 + j * 16, B_LD_ROW);
                    #pragma unroll
                    for (int i = 0; i < 4; ++i)
                        wmma::mma_sync(acc[i][j], af[i], bf, acc[i][j]);
                }
            }
        }
    }
    __syncthreads();

    // ---------------- epilogue: staging 128x128 f32 ----------------
    float* stg = (float*)smem;        // [128][STG_LD] = 67584 B
    #pragma unroll
    for (int i = 0; i < 4; ++i)
        #pragma unroll
        for (int j = 0; j < 4; ++j)
            wmma::store_matrix_sync(stg + (size_t)(wm * 64 + i * 16) * STG_LD + wn * 64 + j * 16,
                                    acc[i][j], STG_LD, wmma::mem_row_major);
    __syncthreads();

    #pragma unroll
    for (int it = 0; it < 16; ++it) {
        int e = it * (NTHR * 8) + tid * 8;        // 0..16383
        if (EPI == 2) {
            int r = e & 127, col = e >> 7;        // r 8-consecutive
            int n = n0 + col;
            float bv = bias[n];
            int m = m0 + r;
            int bb = m >> 14, hw = m & 16383;
            size_t oi = ((size_t)bb * CDIM + n) * 16384 + hw;
            float4 o0, o1;
            const float4 r0 = *(const float4*)(res + oi);
            const float4 r1 = *(const float4*)(res + oi + 4);
            o0.x = stg[(r+0)*STG_LD+col] + bv + r0.x;
            o0.y = stg[(r+1)*STG_LD+col] + bv + r0.y;
            o0.z = stg[(r+2)*STG_LD+col] + bv + r0.z;
            o0.w = stg[(r+3)*STG_LD+col] + bv + r0.w;
            o1.x = stg[(r+4)*STG_LD+col] + bv + r1.x;
            o1.y = stg[(r+5)*STG_LD+col] + bv + r1.y;
            o1.z = stg[(r+6)*STG_LD+col] + bv + r1.z;
            o1.w = stg[(r+7)*STG_LD+col] + bv + r1.w;
            *(float4*)((float*)Cv + oi)     = o0;
            *(float4*)((float*)Cv + oi + 4) = o1;
        } else {
            int col = e & 127, r = e >> 7;        // col 8-aligned consecutive
            int m = m0 + r;
            int n = n0 + col;
            float v[8];
            #pragma unroll
            for (int j = 0; j < 8; ++j) {
                v[j] = stg[r * STG_LD + col + j] + bias[n + j];
                if (EPI == 1)
                    v[j] = 0.5f * v[j] * (1.0f + erff(v[j] * 0.70710678118654752f));
            }
            if (EPI == 3) {
                int bb  = m >> 14;
                int wl  = (m >> 6) & 255;
                int pix = m & 63;
                int q = wl * 32768 + pix * 512 + n;
                size_t base = (size_t)bb * 8388608 + (size_t)(q >> 14) * 16384
                            + (((q >> 10) & 15) * 8 + ((q >> 3) & 7)) * 128
                            + ((q >> 6) & 15) * 8;
                const float4 x0 = *(const float4*)(res + base);
                const float4 x1v = *(const float4*)(res + base + 4);
                float4 o0 = make_float4(v[0]+x0.x, v[1]+x0.y, v[2]+x0.z, v[3]+x0.w);
                float4 o1 = make_float4(v[4]+x1v.x, v[5]+x1v.y, v[6]+x1v.z, v[7]+x1v.w);
                *(float4*)((float*)Cv + base)     = o0;
                *(float4*)((float*)Cv + base + 4) = o1;
            } else {
                uint4 pk; __half2 hh;
                hh = __floats2half2_rn(v[0], v[1]); pk.x = *(unsigned*)&hh;
                hh = __floats2half2_rn(v[2], v[3]); pk.y = *(unsigned*)&hh;
                hh = __floats2half2_rn(v[4], v[5]); pk.z = *(unsigned*)&hh;
                hh = __floats2half2_rn(v[6], v[7]); pk.w = *(unsigned*)&hh;
                *(uint4*)((__half*)Cv + (size_t)m * N + n) = pk;
            }
        }
    }
}

// =====================================================================
// tensor-core attention: one block per (window, head), 64 threads (2 warps).
// =====================================================================
#define QK_LD 40    // halfs
#define S_LD  68    // floats
#define P_LD  72    // halfs

__global__ __launch_bounds__(64)
void attn_tc_kernel(const __half* __restrict__ qkv, const float* __restrict__ bias16,
                    __half* __restrict__ ctx)
{
    __shared__ __align__(16) __half Qs[64 * QK_LD];
    __shared__ __align__(16) __half Ks[64 * QK_LD];
    __shared__ __align__(16) __half Vs[64 * QK_LD];
    __shared__ __align__(16) float  Ss[64 * S_LD];
    __shared__ __align__(16) __half Ps[64 * P_LD];

    int win  = blockIdx.x >> 4;
    int head = blockIdx.x & 15;
    int tid  = threadIdx.x;
    int warp = tid >> 5;

    size_t base = (size_t)win * 64 * QKVN + head * 32;
    #pragma unroll
    for (int i = 0; i < 4; ++i) {
        int idx = i * 64 + tid;
        int tok = idx >> 2, c = idx & 3;
        size_t off = base + (size_t)tok * QKVN + c * 8;
        *(uint4*)(Qs + tok * QK_LD + c * 8) = *(const uint4*)(qkv + off);
        *(uint4*)(Ks + tok * QK_LD + c * 8) = *(const uint4*)(qkv + off + 512);
        *(uint4*)(Vs + tok * QK_LD + c * 8) = *(const uint4*)(qkv + off + 1024);
    }
    __syncthreads();

    {
        wmma::fragment<wmma::accumulator, 16, 16, 16, float> sacc[2][4];
        #pragma unroll
        for (int i = 0; i < 2; ++i)
            #pragma unroll
            for (int j = 0; j < 4; ++j)
                wmma::fill_fragment(sacc[i][j], 0.0f);
        #pragma unroll
        for (int kk = 0; kk < 32; kk += 16) {
            wmma::fragment<wmma::matrix_a, 16, 16, 16, __half, wmma::row_major> af[2];
            wmma::fragment<wmma::matrix_b, 16, 16, 16, __half, wmma::col_major> bf[4];
            #pragma unroll
            for (int i = 0; i < 2; ++i)
                wmma::load_matrix_sync(af[i], Qs + (warp * 32 + i * 16) * QK_LD + kk, QK_LD);
            #pragma unroll
            for (int j = 0; j < 4; ++j)
                wmma::load_matrix_sync(bf[j], Ks + (j * 16) * QK_LD + kk, QK_LD);
            #pragma unroll
            for (int i = 0; i < 2; ++i)
                #pragma unroll
                for (int j = 0; j < 4; ++j)
                    wmma::mma_sync(sacc[i][j], af[i], bf[j], sacc[i][j]);
        }
        #pragma unroll
        for (int i = 0; i < 2; ++i)
            #pragma unroll
            for (int j = 0; j < 4; ++j)
                wmma::store_matrix_sync(Ss + (warp * 32 + i * 16) * S_LD + j * 16,
                                        sacc[i][j], S_LD, wmma::mem_row_major);
    }
    __syncthreads();

    {
        int r = tid;
        const float* brow = bias16 + ((size_t)head * 64 + r) * 64;
        float v[64];
        float mx = -1e30f;
        #pragma unroll
        for (int q = 0; q < 16; ++q) {
            float4 s = *(float4*)(Ss + r * S_LD + q * 4);
            float4 b = *(const float4*)(brow + q * 4);
            v[q*4+0] = s.x * ATTN_SCALE + b.x;
            v[q*4+1] = s.y * ATTN_SCALE + b.y;
            v[q*4+2] = s.z * ATTN_SCALE + b.z;
            v[q*4+3] = s.w * ATTN_SCALE + b.w;
            mx = fmaxf(mx, fmaxf(fmaxf(v[q*4+0], v[q*4+1]), fmaxf(v[q*4+2], v[q*4+3])));
        }
        float sum = 0.0f;
        #pragma unroll
        for (int m = 0; m < 64; ++m) { v[m] = __expf(v[m] - mx); sum += v[m]; }
        float inv = 1.0f / sum;
        #pragma unroll
        for (int q = 0; q < 8; ++q) {
            uint4 pk; __half2 hh;
            hh = __floats2half2_rn(v[q*8+0]*inv, v[q*8+1]*inv); pk.x = *(unsigned*)&hh;
            hh = __floats2half2_rn(v[q*8+2]*inv, v[q*8+3]*inv); pk.y = *(unsigned*)&hh;
            hh = __floats2half2_rn(v[q*8+4]*inv, v[q*8+5]*inv); pk.z = *(unsigned*)&hh;
            hh = __floats2half2_rn(v[q*8+6]*inv, v[q*8+7]*inv); pk.w = *(unsigned*)&hh;
            *(uint4*)(Ps + r * P_LD + q * 8) = pk;
        }
    }
    __syncthreads();

    {
        wmma::fragment<wmma::accumulator, 16, 16, 16, float> oacc[2][2];
        #pragma unroll
        for (int i = 0; i < 2; ++i)
            #pragma unroll
            for (int j = 0; j < 2; ++j)
                wmma::fill_fragment(oacc[i][j], 0.0f);
        #pragma unroll
        for (int kk = 0; kk < 64; kk += 16) {
            wmma::fragment<wmma::matrix_a, 16, 16, 16, __half, wmma::row_major> af[2];
            wmma::fragment<wmma::matrix_b, 16, 16, 16, __half, wmma::row_major> bf[2];
            #pragma unroll
            for (int i = 0; i < 2; ++i)
                wmma::load_matrix_sync(af[i], Ps + (warp * 32 + i * 16) * P_LD + kk, P_LD);
            #pragma unroll
            for (int j = 0; j < 2; ++j)
                wmma::load_matrix_sync(bf[j], Vs + kk * QK_LD + j * 16, QK_LD);
            #pragma unroll
            for (int i = 0; i < 2; ++i)
                #pragma unroll
                for (int j = 0; j < 2; ++j)
                    wmma::mma_sync(oacc[i][j], af[i], bf[j], oacc[i][j]);
        }
        #pragma unroll
        for (int i = 0; i < 2; ++i)
            #pragma unroll
            for (int j = 0; j < 2; ++j)
                wmma::store_matrix_sync(Ss + (warp * 32 + i * 16) * S_LD + j * 16,
                                        oacc[i][j], S_LD, wmma::mem_row_major);
    }
    __syncthreads();

    {
        int r = tid;
        size_t ob = ((size_t)win * 64 + r) * CDIM + head * 32;
        #pragma unroll
        for (int q = 0; q < 4; ++q) {
            float4 a = *(float4*)(Ss + r * S_LD + q * 8);
            float4 b = *(float4*)(Ss + r * S_LD + q * 8 + 4);
            uint4 pk; __half2 hh;
            hh = __floats2half2_rn(a.x, a.y); pk.x = *(unsigned*)&hh;
            hh = __floats2half2_rn(a.z, a.w); pk.y = *(unsigned*)&hh;
            hh = __floats2half2_rn(b.x, b.y); pk.z = *(unsigned*)&hh;
            hh = __floats2half2_rn(b.z, b.w); pk.w = *(unsigned*)&hh;
            *(uint4*)(ctx + ob + q * 8) = pk;
        }
    }
}

// =====================================================================
extern "C" void kernel_launch(void* const* d_in, const int* in_sizes, int n_in,
                              void* d_out, int out_size)
{
    const float* x      = (const float*)d_in[0];
    const float* qkv_w  = (const float*)d_in[1];
    const float* qkv_b  = (const float*)d_in[2];
    const float* proj_w = (const float*)d_in[3];
    const float* proj_b = (const float*)d_in[4];
    const float* relt   = (const float*)d_in[5];
    const float* bn1g   = (const float*)d_in[6];
    const float* bn1b   = (const float*)d_in[7];
    const float* bn1m   = (const float*)d_in[8];
    const float* bn1v   = (const float*)d_in[9];
    const float* mlp_w1 = (const float*)d_in[10];
    const float* mlp_b1 = (const float*)d_in[11];
    const float* mlp_w2 = (const float*)d_in[12];
    const float* mlp_b2 = (const float*)d_in[13];
    const float* bn2g   = (const float*)d_in[14];
    const float* bn2b   = (const float*)d_in[15];
    const float* bn2m   = (const float*)d_in[16];
    const float* bn2v   = (const float*)d_in[17];
    float* out = (float*)d_out;

    __half *p_xw, *p_qkv, *p_ctx, *p_xn2, *p_h, *p_wqkv, *p_wproj, *p_w1, *p_w2;
    float  *p_x1, *p_bias;
    cudaGetSymbolAddress((void**)&p_xw,   g_xw);
    cudaGetSymbolAddress((void**)&p_qkv,  g_qkv);
    cudaGetSymbolAddress((void**)&p_ctx,  g_ctx);
    cudaGetSymbolAddress((void**)&p_x1,   g_x1);
    cudaGetSymbolAddress((void**)&p_xn2,  g_xn2);
    cudaGetSymbolAddress((void**)&p_h,    g_h);
    cudaGetSymbolAddress((void**)&p_wqkv, g_wqkv);
    cudaGetSymbolAddress((void**)&p_wproj,g_wproj);
    cudaGetSymbolAddress((void**)&p_w1,   g_w1);
    cudaGetSymbolAddress((void**)&p_w2,   g_w2);
    cudaGetSymbolAddress((void**)&p_bias, g_bias);

    cudaFuncSetAttribute(gemm_h<false, 0>, cudaFuncAttributeMaxDynamicSharedMemorySize, GEMM_SMEM);
    cudaFuncSetAttribute(gemm_h<false, 3>, cudaFuncAttributeMaxDynamicSharedMemorySize, GEMM_SMEM);
    cudaFuncSetAttribute(gemm_h<true, 1>,  cudaFuncAttributeMaxDynamicSharedMemorySize, GEMM_SMEM);
    cudaFuncSetAttribute(gemm_h<true, 2>,  cudaFuncAttributeMaxDynamicSharedMemorySize, GEMM_SMEM);

    // 0) weight conversions (batched) + bias expansion
    cvt_all_kernel<<<1536, 256>>>(qkv_w, proj_w, mlp_w1, mlp_w2,
                                  p_wqkv, p_wproj, p_w1, p_w2);
    bias_expand_kernel<<<256, 256>>>(relt, p_bias);

    // 1) BN1 + window partition
    prep_kernel<<<NWIN, 256>>>(x, bn1g, bn1b, bn1m, bn1v, p_xw, 1);

    // 2) QKV projection
    gemm_h<false, 0><<<dim3(QKVN / GBN, MTOT / GBM), NTHR, GEMM_SMEM>>>(
        p_xw, p_wqkv, qkv_b, p_qkv, nullptr, MTOT, QKVN, CDIM);

    // 3) windowed attention (tensor cores)
    attn_tc_kernel<<<NWIN * 16, 64>>>(p_qkv, p_bias, p_ctx);

    // 4) proj + window-reverse + x residual -> x1 (NCHW f32), fused
    gemm_h<false, 3><<<dim3(CDIM / GBN, MTOT / GBM), NTHR, GEMM_SMEM>>>(
        p_ctx, p_wproj, proj_b, p_x1, x, MTOT, CDIM, CDIM);

    // 5) BN2 + pixel-major transpose
    prep_kernel<<<NWIN, 256>>>(p_x1, bn2g, bn2b, bn2m, bn2v, p_xn2, 0);

    // 6) FC1 + GELU
    gemm_h<true, 1><<<dim3(CDIM / GBN, MTOT / GBM), NTHR, GEMM_SMEM>>>(
        p_xn2, p_w1, mlp_b1, p_h, nullptr, MTOT, CDIM, CDIM);

    // 7) FC2 + bias + residual -> NCHW output
    gemm_h<true, 2><<<dim3(CDIM / GBN, MTOT / GBM), NTHR, GEMM_SMEM>>>(
        p_h, p_w2, mlp_b2, out, p_x1, MTOT, CDIM, CDIM);
}